// round 6
// baseline (speedup 1.0000x reference)
#include <cuda_runtime.h>
#include <cuda_bf16.h>
#include <cuda_fp16.h>

#define N_USER  50000
#define N_ITEM  100000
#define N_NODES 150000
#define DD      64
#define NLAYER  3
#define NNZ     2400000
#define BB      1024
#define NB_SCAN 587   // ceil(N_NODES/256)
#define WPITCH  132   // padded k-pitch for transposed W (conflict-free LDS)

// Scratch (device globals: allocation-free per harness rules)
__device__ float4 g_E [N_NODES * 16];   // E  [N,64] fp32
__device__ float4 g_LE[N_NODES * 16];   // L_E[N,64] fp32
__device__ uint2  g_Eh[N_NODES * 16];   // E  [N,64] fp16 shadow (4 halves per uint2)
__device__ float  g_mlp[BB * DD];
__device__ int    g_win[N_USER];
// CSR scratch
__device__ int    g_cnt[N_NODES];
__device__ int    g_ptr[N_NODES];
__device__ int    g_cur[N_NODES];
__device__ int    g_bsum[NB_SCAN];
__device__ int    g_bscan[NB_SCAN];
__device__ int2   g_cv[NNZ];            // {col, float_as_int(val)}
// tf32-split transposed weights: [layer][n(64)][k padded to 132]
__device__ unsigned int g_whiT[NLAYER * 64 * WPITCH];
__device__ unsigned int g_wloT[NLAYER * 64 * WPITCH];

__device__ __forceinline__ uint2 pack_half4(float4 v) {
    __half2 a = __floats2half2_rn(v.x, v.y);
    __half2 b = __floats2half2_rn(v.z, v.w);
    uint2 r;
    r.x = *reinterpret_cast<unsigned int*>(&a);
    r.y = *reinterpret_cast<unsigned int*>(&b);
    return r;
}
__device__ __forceinline__ void accum_h4(float4& a, float v, uint2 u) {
    __half2 h01 = *reinterpret_cast<__half2*>(&u.x);
    __half2 h23 = *reinterpret_cast<__half2*>(&u.y);
    float2 f01 = __half22float2(h01);
    float2 f23 = __half22float2(h23);
    a.x += v * f01.x; a.y += v * f01.y;
    a.z += v * f23.x; a.w += v * f23.y;
}

// ---------------- tiny MLP ----------------
__global__ void k_mlp(const float* __restrict__ feat,
                      const float* __restrict__ l1w, const float* __restrict__ l1b,
                      const float* __restrict__ l2w, const float* __restrict__ l2b) {
    __shared__ float h[32];
    int i = blockIdx.x, t = threadIdx.x;
    if (t < 32) {
        float s = l1b[t];
#pragma unroll
        for (int f = 0; f < 4; f++) s += feat[i * 4 + f] * l1w[f * 32 + t];
        h[t] = s;
    }
    __syncthreads();
    float s = l2b[t];
#pragma unroll
    for (int j = 0; j < 32; j++) s += h[j] * l2w[j * DD + t];
    g_mlp[i * DD + t] = s;
}

// ---------------- E = concat(user_emb, item_emb), fp32 + fp16 shadow ----------
__global__ void k_init(const float4* __restrict__ ue, const float4* __restrict__ ie) {
    int i = blockIdx.x * blockDim.x + threadIdx.x;
    const int NU4 = N_USER * 16;
    if (i >= N_NODES * 16) return;
    float4 v = (i < NU4) ? ue[i] : ie[i - NU4];
    g_E[i] = v;
    g_Eh[i] = pack_half4(v);
}

// ---------------- last-wins scatter of user updates ----------------
__global__ void k_win_reset(const int* __restrict__ ui) {
    int i = blockIdx.x * blockDim.x + threadIdx.x;
    if (i < BB) g_win[ui[i]] = -1;
}
__global__ void k_win_max(const int* __restrict__ ui) {
    int i = blockIdx.x * blockDim.x + threadIdx.x;
    if (i < BB) atomicMax(&g_win[ui[i]], i);
}
__global__ void k_apply(const int* __restrict__ ui, const float* __restrict__ user_emb,
                        const float* __restrict__ ratio) {
    int i = blockIdx.x, t = threadIdx.x;  // 64 threads
    int u = ui[i];
    if (g_win[u] != i) return;
    float r = *ratio;
    float* E = (float*)g_E;
    float v = user_emb[u * DD + t] * (1.0f - r) + g_mlp[i * DD + t] * r;
    E[u * DD + t] = v;
    ((__half*)g_Eh)[u * DD + t] = __float2half_rn(v);
}

// ================= CSR build =================
__global__ void k_cnt_zero() {
    int i = blockIdx.x * blockDim.x + threadIdx.x;
    if (i < N_NODES) g_cnt[i] = 0;
}
__global__ void k_hist(const int* __restrict__ row) {
    int e = blockIdx.x * blockDim.x + threadIdx.x;
    if (e < NNZ) atomicAdd(&g_cnt[row[e]], 1);
}
__global__ void k_scan1() {
    __shared__ int s[256];
    int t = threadIdx.x;
    int i = blockIdx.x * 256 + t;
    int v = (i < N_NODES) ? g_cnt[i] : 0;
    s[t] = v;
    __syncthreads();
#pragma unroll
    for (int off = 1; off < 256; off <<= 1) {
        int u = (t >= off) ? s[t - off] : 0;
        __syncthreads();
        s[t] += u;
        __syncthreads();
    }
    if (i < N_NODES) g_ptr[i] = s[t] - v;
    if (t == 255) g_bsum[blockIdx.x] = s[255];
}
__global__ void k_scan2() {
    __shared__ int s[1024];
    int t = threadIdx.x;
    int v = (t < NB_SCAN) ? g_bsum[t] : 0;
    s[t] = v;
    __syncthreads();
#pragma unroll
    for (int off = 1; off < 1024; off <<= 1) {
        int u = (t >= off) ? s[t - off] : 0;
        __syncthreads();
        s[t] += u;
        __syncthreads();
    }
    if (t < NB_SCAN) g_bscan[t] = s[t] - v;
}
__global__ void k_scan3() {
    int i = blockIdx.x * blockDim.x + threadIdx.x;
    if (i < N_NODES) {
        int p = g_ptr[i] + g_bscan[i >> 8];
        g_ptr[i] = p;
        g_cur[i] = p;
    }
}
__global__ void k_fill(const int* __restrict__ row, const int* __restrict__ col,
                       const float* __restrict__ val) {
    int e = blockIdx.x * blockDim.x + threadIdx.x;
    if (e >= NNZ) return;
    int r = row[e];
    int pos = atomicAdd(&g_cur[r], 1);
    g_cv[pos] = make_int2(col[e], __float_as_int(val[e]));
}

// ================= CSR SpMM (fp16 gather): 2 rows/warp, 16 lanes x 4 halves ====
__global__ void __launch_bounds__(256) k_spmm_csr() {
    int w = (blockIdx.x * blockDim.x + threadIdx.x) >> 5;
    int lane = threadIdx.x & 31;
    int half = lane >> 4;       // which row this half-warp owns
    int hl = lane & 15;         // lane within half (4-half slot)
    int row = w * 2 + half;
    if (row >= N_NODES) return;
    int start = g_ptr[row];
    int end = start + g_cnt[row];
    const uint2* __restrict__ Eh = (const uint2*)g_Eh;

    float4 a0 = make_float4(0.f, 0.f, 0.f, 0.f);
    float4 a1 = make_float4(0.f, 0.f, 0.f, 0.f);
    float4 a2 = make_float4(0.f, 0.f, 0.f, 0.f);
    float4 a3 = make_float4(0.f, 0.f, 0.f, 0.f);
    int e = start;
    for (; e + 8 <= end; e += 8) {
        int2 c0 = g_cv[e],     c1 = g_cv[e + 1], c2 = g_cv[e + 2], c3 = g_cv[e + 3];
        int2 c4 = g_cv[e + 4], c5 = g_cv[e + 5], c6 = g_cv[e + 6], c7 = g_cv[e + 7];
        uint2 x0 = Eh[c0.x * 16 + hl];
        uint2 x1 = Eh[c1.x * 16 + hl];
        uint2 x2 = Eh[c2.x * 16 + hl];
        uint2 x3 = Eh[c3.x * 16 + hl];
        uint2 x4 = Eh[c4.x * 16 + hl];
        uint2 x5 = Eh[c5.x * 16 + hl];
        uint2 x6 = Eh[c6.x * 16 + hl];
        uint2 x7 = Eh[c7.x * 16 + hl];
        accum_h4(a0, __int_as_float(c0.y), x0);
        accum_h4(a1, __int_as_float(c1.y), x1);
        accum_h4(a2, __int_as_float(c2.y), x2);
        accum_h4(a3, __int_as_float(c3.y), x3);
        accum_h4(a0, __int_as_float(c4.y), x4);
        accum_h4(a1, __int_as_float(c5.y), x5);
        accum_h4(a2, __int_as_float(c6.y), x6);
        accum_h4(a3, __int_as_float(c7.y), x7);
    }
    for (; e + 2 <= end; e += 2) {
        int2 c0 = g_cv[e], c1 = g_cv[e + 1];
        uint2 x0 = Eh[c0.x * 16 + hl];
        uint2 x1 = Eh[c1.x * 16 + hl];
        accum_h4(a0, __int_as_float(c0.y), x0);
        accum_h4(a1, __int_as_float(c1.y), x1);
    }
    if (e < end) {
        int2 c0 = g_cv[e];
        uint2 x0 = Eh[c0.x * 16 + hl];
        accum_h4(a0, __int_as_float(c0.y), x0);
    }
    a0.x += a1.x + a2.x + a3.x;
    a0.y += a1.y + a2.y + a3.y;
    a0.z += a1.z + a2.z + a3.z;
    a0.w += a1.w + a2.w + a3.w;
    g_LE[row * 16 + hl] = a0;
}

// ================= W split (hi/lo tf32), transposed + padded =================
__global__ void k_wsplit(const float* __restrict__ w1, const float* __restrict__ w2) {
    int idx = blockIdx.x * 256 + threadIdx.x;  // over NLAYER*64*128
    if (idx >= NLAYER * 64 * 128) return;
    int layer = idx / (64 * 128);
    int rem = idx % (64 * 128);
    int n = rem / 128, k = rem % 128;
    float w = (k < 64) ? w1[layer * 4096 + k * 64 + n]
                       : w2[layer * 4096 + (k - 64) * 64 + n];
    unsigned int hi;
    asm("cvt.rna.tf32.f32 %0, %1;" : "=r"(hi) : "f"(w));
    float lof = w - __uint_as_float(hi);
    unsigned int lo;
    asm("cvt.rna.tf32.f32 %0, %1;" : "=r"(lo) : "f"(lof));
    g_whiT[layer * 64 * WPITCH + n * WPITCH + k] = hi;
    g_wloT[layer * 64 * WPITCH + n * WPITCH + k] = lo;
}

// ================= tensor-core GEMM (3xTF32) + bias + leaky, in-place on E ====
#define MMA_TF32(C, A0, A1, A2, A3, B0, B1)                                      \
    asm volatile("mma.sync.aligned.m16n8k8.row.col.f32.tf32.tf32.f32 "           \
                 "{%0,%1,%2,%3}, {%4,%5,%6,%7}, {%8,%9}, {%0,%1,%2,%3};"         \
                 : "+f"(C[0]), "+f"(C[1]), "+f"(C[2]), "+f"(C[3])                \
                 : "r"(A0), "r"(A1), "r"(A2), "r"(A3), "r"(B0), "r"(B1))

__global__ void __launch_bounds__(256) k_gemm_mma(int layer,
                                                  const float* __restrict__ b1,
                                                  const float* __restrict__ b2) {
    __shared__ unsigned int whi[64 * WPITCH];
    __shared__ float bs[64];
    int t = threadIdx.x;
    {
        const uint4* s4 = (const uint4*)(g_whiT + layer * 64 * WPITCH);
        uint4* d4 = (uint4*)whi;
        for (int i = t; i < 64 * WPITCH / 4; i += 256) d4[i] = s4[i];
        if (t < 64) bs[t] = b1[t] + b2[t];
    }
    __syncthreads();

    int warp = t >> 5, lane = t & 31;
    int q = lane & 3, g = lane >> 2;
    int base = blockIdx.x * 128 + warp * 16;
    int r0 = base + g, r1 = base + g + 8;
    int r0c = min(r0, N_NODES - 1), r1c = min(r1, N_NODES - 1);
    const float* __restrict__ Ei = (const float*)g_E;
    const float* __restrict__ LE = (const float*)g_LE;
    const unsigned int* __restrict__ wlo = g_wloT + layer * 64 * WPITCH;

    float C[8][4];
#pragma unroll
    for (int i = 0; i < 8; i++)
#pragma unroll
        for (int j = 0; j < 4; j++) C[i][j] = 0.f;

#pragma unroll
    for (int kk = 0; kk < 16; kk++) {
        int half = kk >> 3;            // 0: (LE+E) half, 1: (LE*E) half
        int cb = (kk & 7) * 8;
        int c0 = cb + q, c1 = cb + q + 4;
        float l00 = LE[r0c * 64 + c0], e00 = Ei[r0c * 64 + c0];
        float l10 = LE[r1c * 64 + c0], e10 = Ei[r1c * 64 + c0];
        float l01 = LE[r0c * 64 + c1], e01 = Ei[r0c * 64 + c1];
        float l11 = LE[r1c * 64 + c1], e11 = Ei[r1c * 64 + c1];
        float x0 = half ? l00 * e00 : l00 + e00;
        float x1 = half ? l10 * e10 : l10 + e10;
        float x2 = half ? l01 * e01 : l01 + e01;
        float x3 = half ? l11 * e11 : l11 + e11;
        unsigned int ah0, ah1, ah2, ah3, al0, al1, al2, al3;
        asm("cvt.rna.tf32.f32 %0, %1;" : "=r"(ah0) : "f"(x0));
        asm("cvt.rna.tf32.f32 %0, %1;" : "=r"(ah1) : "f"(x1));
        asm("cvt.rna.tf32.f32 %0, %1;" : "=r"(ah2) : "f"(x2));
        asm("cvt.rna.tf32.f32 %0, %1;" : "=r"(ah3) : "f"(x3));
        float y0 = x0 - __uint_as_float(ah0);
        float y1 = x1 - __uint_as_float(ah1);
        float y2 = x2 - __uint_as_float(ah2);
        float y3 = x3 - __uint_as_float(ah3);
        asm("cvt.rna.tf32.f32 %0, %1;" : "=r"(al0) : "f"(y0));
        asm("cvt.rna.tf32.f32 %0, %1;" : "=r"(al1) : "f"(y1));
        asm("cvt.rna.tf32.f32 %0, %1;" : "=r"(al2) : "f"(y2));
        asm("cvt.rna.tf32.f32 %0, %1;" : "=r"(al3) : "f"(y3));
        int krow = kk * 8 + q;
#pragma unroll
        for (int nt = 0; nt < 8; nt++) {
            int wb = (nt * 8 + g) * WPITCH + krow;
            unsigned int bh0 = whi[wb], bh1 = whi[wb + 4];
            unsigned int bl0 = __ldg(&wlo[wb]), bl1 = __ldg(&wlo[wb + 4]);
            MMA_TF32(C[nt], ah0, ah1, ah2, ah3, bh0, bh1);
            MMA_TF32(C[nt], al0, al1, al2, al3, bh0, bh1);
            MMA_TF32(C[nt], ah0, ah1, ah2, ah3, bl0, bl1);
        }
    }

    float* Eo = (float*)g_E;
    __half2* Eoh = (__half2*)g_Eh;
#pragma unroll
    for (int nt = 0; nt < 8; nt++) {
        int col = nt * 8 + 2 * q;
        float b0v = bs[col], b1v = bs[col + 1];
        float v00 = C[nt][0] + b0v, v01 = C[nt][1] + b1v;
        float v10 = C[nt][2] + b0v, v11 = C[nt][3] + b1v;
        v00 = v00 >= 0.f ? v00 : 0.2f * v00;
        v01 = v01 >= 0.f ? v01 : 0.2f * v01;
        v10 = v10 >= 0.f ? v10 : 0.2f * v10;
        v11 = v11 >= 0.f ? v11 : 0.2f * v11;
        if (r0 < N_NODES) {
            *(float2*)(Eo + r0 * 64 + col) = make_float2(v00, v01);
            Eoh[r0 * 32 + col / 2] = __floats2half2_rn(v00, v01);
        }
        if (r1 < N_NODES) {
            *(float2*)(Eo + r1 * 64 + col) = make_float2(v10, v11);
            Eoh[r1 * 32 + col / 2] = __floats2half2_rn(v10, v11);
        }
    }
}

// ---------------- gather (with optional row-normalize) into output ----------------
__global__ void k_gather(const int* __restrict__ user_idx, const int* __restrict__ pos_idx,
                         const int* __restrict__ neg_idx, float* __restrict__ out, int layer) {
    int w = (blockIdx.x * blockDim.x + threadIdx.x) >> 5;
    int lane = threadIdx.x & 31;
    if (w >= 3 * BB) return;
    int node;
    if (w < BB)          node = user_idx[w];
    else if (w < 2 * BB) node = N_USER + pos_idx[w - BB];
    else                 node = N_USER + neg_idx[w - 2 * BB];
    float2 v = ((const float2*)g_E)[node * 32 + lane];
    float scale = 1.0f;
    if (layer > 0) {
        float s = v.x * v.x + v.y * v.y;
#pragma unroll
        for (int o = 16; o; o >>= 1) s += __shfl_xor_sync(0xffffffffu, s, o);
        scale = 1.0f / fmaxf(sqrtf(s), 1e-12f);
    }
    ((float2*)(out + (size_t)w * 256 + layer * 64))[lane] = make_float2(v.x * scale, v.y * scale);
}

extern "C" void kernel_launch(void* const* d_in, const int* in_sizes, int n_in,
                              void* d_out, int out_size) {
    const float *user_emb, *item_emb, *lin1_w, *lin1_b, *lin2_w, *lin2_b;
    const float *w1, *b1, *w2, *b2, *lap_val, *user_feat, *mlp_ratio;
    const int *lap_row, *lap_col, *user_idx, *pos_idx, *neg_idx;

    if (in_sizes[2] == 4096) {
        user_emb = (const float*)d_in[0];  item_emb = (const float*)d_in[1];
        user_feat= (const float*)d_in[2];
        lin1_w   = (const float*)d_in[3];  lin1_b   = (const float*)d_in[4];
        lin2_w   = (const float*)d_in[5];  lin2_b   = (const float*)d_in[6];
        w1 = (const float*)d_in[7];  b1 = (const float*)d_in[8];
        w2 = (const float*)d_in[9];  b2 = (const float*)d_in[10];
        lap_val  = (const float*)d_in[11]; mlp_ratio = (const float*)d_in[12];
        lap_row  = (const int*)d_in[13];   lap_col   = (const int*)d_in[14];
        user_idx = (const int*)d_in[15];   pos_idx   = (const int*)d_in[16];
        neg_idx  = (const int*)d_in[17];
    } else {
        user_emb = (const float*)d_in[0];  item_emb = (const float*)d_in[1];
        lin1_w   = (const float*)d_in[2];  lin1_b   = (const float*)d_in[3];
        lin2_w   = (const float*)d_in[4];  lin2_b   = (const float*)d_in[5];
        w1 = (const float*)d_in[6];  b1 = (const float*)d_in[7];
        w2 = (const float*)d_in[8];  b2 = (const float*)d_in[9];
        lap_row  = (const int*)d_in[10];   lap_col  = (const int*)d_in[11];
        lap_val  = (const float*)d_in[12];
        user_idx = (const int*)d_in[13];   user_feat = (const float*)d_in[14];
        pos_idx  = (const int*)d_in[15];   neg_idx   = (const int*)d_in[16];
        mlp_ratio= (const float*)d_in[17];
    }

    float* out = (float*)d_out;
    const int V4 = N_NODES * 16;

    // CSR build + weight split (independent of E; do them first)
    k_cnt_zero<<<NB_SCAN, 256>>>();
    k_hist<<<(NNZ + 255) / 256, 256>>>(lap_row);
    k_scan1<<<NB_SCAN, 256>>>();
    k_scan2<<<1, 1024>>>();
    k_scan3<<<NB_SCAN, 256>>>();
    k_fill<<<(NNZ + 255) / 256, 256>>>(lap_row, lap_col, lap_val);
    k_wsplit<<<(NLAYER * 64 * 128 + 255) / 256, 256>>>(w1, w2);

    k_mlp<<<BB, 64>>>(user_feat, lin1_w, lin1_b, lin2_w, lin2_b);
    k_init<<<(V4 + 255) / 256, 256>>>((const float4*)user_emb, (const float4*)item_emb);
    k_win_reset<<<(BB + 255) / 256, 256>>>(user_idx);
    k_win_max<<<(BB + 255) / 256, 256>>>(user_idx);
    k_apply<<<BB, 64>>>(user_idx, user_emb, mlp_ratio);
    k_gather<<<(3 * BB * 32 + 255) / 256, 256>>>(user_idx, pos_idx, neg_idx, out, 0);

    for (int k = 0; k < NLAYER; k++) {
        k_spmm_csr<<<(N_NODES / 2 + 7) / 8, 256>>>();
        k_gemm_mma<<<(N_NODES + 127) / 128, 256>>>(k, b1 + k * 64, b2 + k * 64);
        k_gather<<<(3 * BB * 32 + 255) / 256, 256>>>(user_idx, pos_idx, neg_idx, out, k + 1);
    }
}

// round 7
// speedup vs baseline: 1.0293x; 1.0293x over previous
#include <cuda_runtime.h>
#include <cuda_bf16.h>

#define N_USER  50000
#define N_ITEM  100000
#define N_NODES 150000
#define DD      64
#define NLAYER  3
#define NNZ     2400000
#define BB      1024
#define NB_SCAN 587   // ceil(N_NODES/256)
#define WPITCH  132   // padded k-pitch for transposed W (conflict-free LDS)

// Scratch (device globals: allocation-free per harness rules)
__device__ float4 g_E [N_NODES * 16];   // E  [N,64] as float4
__device__ float4 g_LE[N_NODES * 16];   // L_E[N,64] as float4
__device__ float  g_mlp[BB * DD];
__device__ int    g_win[N_USER];
// CSR scratch
__device__ int    g_cnt[N_NODES];
__device__ int    g_ptr[N_NODES];
__device__ int    g_eoff[NNZ];          // within-row slot from hist atomic
__device__ int    g_bsum[NB_SCAN];
__device__ int    g_bscan[NB_SCAN];
__device__ int2   g_cv[NNZ];            // {col, float_as_int(val)}
// tf32-split transposed weights: [layer][n(64)][k padded to 132]
__device__ unsigned int g_whiT[NLAYER * 64 * WPITCH];
__device__ unsigned int g_wloT[NLAYER * 64 * WPITCH];

// ---------------- tiny MLP ----------------
__global__ void k_mlp(const float* __restrict__ feat,
                      const float* __restrict__ l1w, const float* __restrict__ l1b,
                      const float* __restrict__ l2w, const float* __restrict__ l2b) {
    __shared__ float h[32];
    int i = blockIdx.x, t = threadIdx.x;
    if (t < 32) {
        float s = l1b[t];
#pragma unroll
        for (int f = 0; f < 4; f++) s += feat[i * 4 + f] * l1w[f * 32 + t];
        h[t] = s;
    }
    __syncthreads();
    float s = l2b[t];
#pragma unroll
    for (int j = 0; j < 32; j++) s += h[j] * l2w[j * DD + t];
    g_mlp[i * DD + t] = s;
}

// ---------------- E = concat(user_emb, item_emb) ----------------
__global__ void k_init(const float4* __restrict__ ue, const float4* __restrict__ ie) {
    int i = blockIdx.x * blockDim.x + threadIdx.x;
    const int NU4 = N_USER * 16;
    if (i < NU4) g_E[i] = ue[i];
    else if (i < N_NODES * 16) g_E[i] = ie[i - NU4];
}

// ---------------- last-wins scatter of user updates ----------------
__global__ void k_win_reset(const int* __restrict__ ui) {
    int i = blockIdx.x * blockDim.x + threadIdx.x;
    if (i < BB) g_win[ui[i]] = -1;
}
__global__ void k_win_max(const int* __restrict__ ui) {
    int i = blockIdx.x * blockDim.x + threadIdx.x;
    if (i < BB) atomicMax(&g_win[ui[i]], i);
}
__global__ void k_apply(const int* __restrict__ ui, const float* __restrict__ user_emb,
                        const float* __restrict__ ratio) {
    int i = blockIdx.x, t = threadIdx.x;  // 64 threads
    int u = ui[i];
    if (g_win[u] != i) return;
    float r = *ratio;
    float* E = (float*)g_E;
    E[u * DD + t] = user_emb[u * DD + t] * (1.0f - r) + g_mlp[i * DD + t] * r;
}

// ================= CSR build =================
__global__ void k_cnt_zero() {
    int i = blockIdx.x * blockDim.x + threadIdx.x;
    if (i < N_NODES) g_cnt[i] = 0;
}
// histogram; atomic return value = within-row slot (saved for atomic-free fill)
__global__ void k_hist(const int* __restrict__ row) {
    int e = blockIdx.x * blockDim.x + threadIdx.x;
    if (e < NNZ) g_eoff[e] = atomicAdd(&g_cnt[row[e]], 1);
}
__global__ void k_scan1() {
    __shared__ int s[256];
    int t = threadIdx.x;
    int i = blockIdx.x * 256 + t;
    int v = (i < N_NODES) ? g_cnt[i] : 0;
    s[t] = v;
    __syncthreads();
#pragma unroll
    for (int off = 1; off < 256; off <<= 1) {
        int u = (t >= off) ? s[t - off] : 0;
        __syncthreads();
        s[t] += u;
        __syncthreads();
    }
    if (i < N_NODES) g_ptr[i] = s[t] - v;
    if (t == 255) g_bsum[blockIdx.x] = s[255];
}
__global__ void k_scan2() {
    __shared__ int s[1024];
    int t = threadIdx.x;
    int v = (t < NB_SCAN) ? g_bsum[t] : 0;
    s[t] = v;
    __syncthreads();
#pragma unroll
    for (int off = 1; off < 1024; off <<= 1) {
        int u = (t >= off) ? s[t - off] : 0;
        __syncthreads();
        s[t] += u;
        __syncthreads();
    }
    if (t < NB_SCAN) g_bscan[t] = s[t] - v;
}
__global__ void k_scan3() {
    int i = blockIdx.x * blockDim.x + threadIdx.x;
    if (i < N_NODES) g_ptr[i] += g_bscan[i >> 8];
}
// atomic-free fill using saved within-row offsets
__global__ void k_fill(const int* __restrict__ row, const int* __restrict__ col,
                       const float* __restrict__ val) {
    int e = blockIdx.x * blockDim.x + threadIdx.x;
    if (e >= NNZ) return;
    int r = row[e];
    int pos = g_ptr[r] + g_eoff[e];
    g_cv[pos] = make_int2(col[e], __float_as_int(val[e]));
}

// ================= CSR SpMM: 2 rows/warp, 16 lanes x float4, unroll 8 =========
__global__ void __launch_bounds__(256) k_spmm_csr() {
    int w = (blockIdx.x * blockDim.x + threadIdx.x) >> 5;
    int lane = threadIdx.x & 31;
    int half = lane >> 4;       // which row this half-warp owns
    int hl = lane & 15;         // lane within half (float4 slot)
    int row = w * 2 + half;
    if (row >= N_NODES) return;
    int start = g_ptr[row];
    int end = start + g_cnt[row];
    const float4* __restrict__ E4 = (const float4*)g_E;

    float4 a0 = make_float4(0.f, 0.f, 0.f, 0.f);
    float4 a1 = make_float4(0.f, 0.f, 0.f, 0.f);
    float4 a2 = make_float4(0.f, 0.f, 0.f, 0.f);
    float4 a3 = make_float4(0.f, 0.f, 0.f, 0.f);
    int e = start;
    for (; e + 8 <= end; e += 8) {
        int2 c0 = g_cv[e],     c1 = g_cv[e + 1], c2 = g_cv[e + 2], c3 = g_cv[e + 3];
        int2 c4 = g_cv[e + 4], c5 = g_cv[e + 5], c6 = g_cv[e + 6], c7 = g_cv[e + 7];
        float4 x0 = E4[c0.x * 16 + hl];
        float4 x1 = E4[c1.x * 16 + hl];
        float4 x2 = E4[c2.x * 16 + hl];
        float4 x3 = E4[c3.x * 16 + hl];
        float4 x4 = E4[c4.x * 16 + hl];
        float4 x5 = E4[c5.x * 16 + hl];
        float4 x6 = E4[c6.x * 16 + hl];
        float4 x7 = E4[c7.x * 16 + hl];
        float v0 = __int_as_float(c0.y), v1 = __int_as_float(c1.y);
        float v2 = __int_as_float(c2.y), v3 = __int_as_float(c3.y);
        float v4 = __int_as_float(c4.y), v5 = __int_as_float(c5.y);
        float v6 = __int_as_float(c6.y), v7 = __int_as_float(c7.y);
        a0.x += v0 * x0.x; a0.y += v0 * x0.y; a0.z += v0 * x0.z; a0.w += v0 * x0.w;
        a1.x += v1 * x1.x; a1.y += v1 * x1.y; a1.z += v1 * x1.z; a1.w += v1 * x1.w;
        a2.x += v2 * x2.x; a2.y += v2 * x2.y; a2.z += v2 * x2.z; a2.w += v2 * x2.w;
        a3.x += v3 * x3.x; a3.y += v3 * x3.y; a3.z += v3 * x3.z; a3.w += v3 * x3.w;
        a0.x += v4 * x4.x; a0.y += v4 * x4.y; a0.z += v4 * x4.z; a0.w += v4 * x4.w;
        a1.x += v5 * x5.x; a1.y += v5 * x5.y; a1.z += v5 * x5.z; a1.w += v5 * x5.w;
        a2.x += v6 * x6.x; a2.y += v6 * x6.y; a2.z += v6 * x6.z; a2.w += v6 * x6.w;
        a3.x += v7 * x7.x; a3.y += v7 * x7.y; a3.z += v7 * x7.z; a3.w += v7 * x7.w;
    }
    for (; e + 2 <= end; e += 2) {
        int2 c0 = g_cv[e], c1 = g_cv[e + 1];
        float4 x0 = E4[c0.x * 16 + hl];
        float4 x1 = E4[c1.x * 16 + hl];
        float v0 = __int_as_float(c0.y), v1 = __int_as_float(c1.y);
        a0.x += v0 * x0.x; a0.y += v0 * x0.y; a0.z += v0 * x0.z; a0.w += v0 * x0.w;
        a1.x += v1 * x1.x; a1.y += v1 * x1.y; a1.z += v1 * x1.z; a1.w += v1 * x1.w;
    }
    if (e < end) {
        int2 c0 = g_cv[e];
        float4 x0 = E4[c0.x * 16 + hl];
        float v0 = __int_as_float(c0.y);
        a0.x += v0 * x0.x; a0.y += v0 * x0.y; a0.z += v0 * x0.z; a0.w += v0 * x0.w;
    }
    a0.x += a1.x + a2.x + a3.x;
    a0.y += a1.y + a2.y + a3.y;
    a0.z += a1.z + a2.z + a3.z;
    a0.w += a1.w + a2.w + a3.w;
    g_LE[row * 16 + hl] = a0;
}

// ================= W split (hi/lo tf32), transposed + padded =================
__global__ void k_wsplit(const float* __restrict__ w1, const float* __restrict__ w2) {
    int idx = blockIdx.x * 256 + threadIdx.x;  // over NLAYER*64*128
    if (idx >= NLAYER * 64 * 128) return;
    int layer = idx / (64 * 128);
    int rem = idx % (64 * 128);
    int n = rem / 128, k = rem % 128;
    float w = (k < 64) ? w1[layer * 4096 + k * 64 + n]
                       : w2[layer * 4096 + (k - 64) * 64 + n];
    unsigned int hi;
    asm("cvt.rna.tf32.f32 %0, %1;" : "=r"(hi) : "f"(w));
    float lof = w - __uint_as_float(hi);
    unsigned int lo;
    asm("cvt.rna.tf32.f32 %0, %1;" : "=r"(lo) : "f"(lof));
    g_whiT[layer * 64 * WPITCH + n * WPITCH + k] = hi;
    g_wloT[layer * 64 * WPITCH + n * WPITCH + k] = lo;
}

// ================= tensor-core GEMM (3xTF32) + bias + leaky, in-place on E ====
// C[150K x 64] = [LE+E | LE*E] @ [w1;w2], one warp per 16 rows, m16n8k8 mma
#define MMA_TF32(C, A0, A1, A2, A3, B0, B1)                                      \
    asm volatile("mma.sync.aligned.m16n8k8.row.col.f32.tf32.tf32.f32 "           \
                 "{%0,%1,%2,%3}, {%4,%5,%6,%7}, {%8,%9}, {%0,%1,%2,%3};"         \
                 : "+f"(C[0]), "+f"(C[1]), "+f"(C[2]), "+f"(C[3])                \
                 : "r"(A0), "r"(A1), "r"(A2), "r"(A3), "r"(B0), "r"(B1))

__global__ void __launch_bounds__(256) k_gemm_mma(int layer,
                                                  const float* __restrict__ b1,
                                                  const float* __restrict__ b2) {
    __shared__ unsigned int whi[64 * WPITCH];
    __shared__ float bs[64];
    int t = threadIdx.x;
    {
        const uint4* s4 = (const uint4*)(g_whiT + layer * 64 * WPITCH);
        uint4* d4 = (uint4*)whi;
        for (int i = t; i < 64 * WPITCH / 4; i += 256) d4[i] = s4[i];
        if (t < 64) bs[t] = b1[t] + b2[t];
    }
    __syncthreads();

    int warp = t >> 5, lane = t & 31;
    int q = lane & 3, g = lane >> 2;
    int base = blockIdx.x * 128 + warp * 16;
    int r0 = base + g, r1 = base + g + 8;
    int r0c = min(r0, N_NODES - 1), r1c = min(r1, N_NODES - 1);
    const float* __restrict__ Ei = (const float*)g_E;
    const float* __restrict__ LE = (const float*)g_LE;
    const unsigned int* __restrict__ wlo = g_wloT + layer * 64 * WPITCH;

    float C[8][4];
#pragma unroll
    for (int i = 0; i < 8; i++)
#pragma unroll
        for (int j = 0; j < 4; j++) C[i][j] = 0.f;

#pragma unroll
    for (int kk = 0; kk < 16; kk++) {
        int half = kk >> 3;            // 0: (LE+E) half, 1: (LE*E) half
        int cb = (kk & 7) * 8;
        int c0 = cb + q, c1 = cb + q + 4;
        float l00 = LE[r0c * 64 + c0], e00 = Ei[r0c * 64 + c0];
        float l10 = LE[r1c * 64 + c0], e10 = Ei[r1c * 64 + c0];
        float l01 = LE[r0c * 64 + c1], e01 = Ei[r0c * 64 + c1];
        float l11 = LE[r1c * 64 + c1], e11 = Ei[r1c * 64 + c1];
        float x0 = half ? l00 * e00 : l00 + e00;
        float x1 = half ? l10 * e10 : l10 + e10;
        float x2 = half ? l01 * e01 : l01 + e01;
        float x3 = half ? l11 * e11 : l11 + e11;
        unsigned int ah0, ah1, ah2, ah3, al0, al1, al2, al3;
        asm("cvt.rna.tf32.f32 %0, %1;" : "=r"(ah0) : "f"(x0));
        asm("cvt.rna.tf32.f32 %0, %1;" : "=r"(ah1) : "f"(x1));
        asm("cvt.rna.tf32.f32 %0, %1;" : "=r"(ah2) : "f"(x2));
        asm("cvt.rna.tf32.f32 %0, %1;" : "=r"(ah3) : "f"(x3));
        float y0 = x0 - __uint_as_float(ah0);
        float y1 = x1 - __uint_as_float(ah1);
        float y2 = x2 - __uint_as_float(ah2);
        float y3 = x3 - __uint_as_float(ah3);
        asm("cvt.rna.tf32.f32 %0, %1;" : "=r"(al0) : "f"(y0));
        asm("cvt.rna.tf32.f32 %0, %1;" : "=r"(al1) : "f"(y1));
        asm("cvt.rna.tf32.f32 %0, %1;" : "=r"(al2) : "f"(y2));
        asm("cvt.rna.tf32.f32 %0, %1;" : "=r"(al3) : "f"(y3));
        int krow = kk * 8 + q;
#pragma unroll
        for (int nt = 0; nt < 8; nt++) {
            int wb = (nt * 8 + g) * WPITCH + krow;
            unsigned int bh0 = whi[wb], bh1 = whi[wb + 4];
            unsigned int bl0 = __ldg(&wlo[wb]), bl1 = __ldg(&wlo[wb + 4]);
            MMA_TF32(C[nt], ah0, ah1, ah2, ah3, bh0, bh1);
            MMA_TF32(C[nt], al0, al1, al2, al3, bh0, bh1);
            MMA_TF32(C[nt], ah0, ah1, ah2, ah3, bl0, bl1);
        }
    }

    float* Eo = (float*)g_E;
#pragma unroll
    for (int nt = 0; nt < 8; nt++) {
        int col = nt * 8 + 2 * q;
        float b0v = bs[col], b1v = bs[col + 1];
        float v00 = C[nt][0] + b0v, v01 = C[nt][1] + b1v;
        float v10 = C[nt][2] + b0v, v11 = C[nt][3] + b1v;
        v00 = v00 >= 0.f ? v00 : 0.2f * v00;
        v01 = v01 >= 0.f ? v01 : 0.2f * v01;
        v10 = v10 >= 0.f ? v10 : 0.2f * v10;
        v11 = v11 >= 0.f ? v11 : 0.2f * v11;
        if (r0 < N_NODES) *(float2*)(Eo + r0 * 64 + col) = make_float2(v00, v01);
        if (r1 < N_NODES) *(float2*)(Eo + r1 * 64 + col) = make_float2(v10, v11);
    }
}

// ---------------- gather (with optional row-normalize) into output ----------------
__global__ void k_gather(const int* __restrict__ user_idx, const int* __restrict__ pos_idx,
                         const int* __restrict__ neg_idx, float* __restrict__ out, int layer) {
    int w = (blockIdx.x * blockDim.x + threadIdx.x) >> 5;
    int lane = threadIdx.x & 31;
    if (w >= 3 * BB) return;
    int node;
    if (w < BB)          node = user_idx[w];
    else if (w < 2 * BB) node = N_USER + pos_idx[w - BB];
    else                 node = N_USER + neg_idx[w - 2 * BB];
    float2 v = ((const float2*)g_E)[node * 32 + lane];
    float scale = 1.0f;
    if (layer > 0) {
        float s = v.x * v.x + v.y * v.y;
#pragma unroll
        for (int o = 16; o; o >>= 1) s += __shfl_xor_sync(0xffffffffu, s, o);
        scale = 1.0f / fmaxf(sqrtf(s), 1e-12f);
    }
    ((float2*)(out + (size_t)w * 256 + layer * 64))[lane] = make_float2(v.x * scale, v.y * scale);
}

extern "C" void kernel_launch(void* const* d_in, const int* in_sizes, int n_in,
                              void* d_out, int out_size) {
    const float *user_emb, *item_emb, *lin1_w, *lin1_b, *lin2_w, *lin2_b;
    const float *w1, *b1, *w2, *b2, *lap_val, *user_feat, *mlp_ratio;
    const int *lap_row, *lap_col, *user_idx, *pos_idx, *neg_idx;

    if (in_sizes[2] == 4096) {
        user_emb = (const float*)d_in[0];  item_emb = (const float*)d_in[1];
        user_feat= (const float*)d_in[2];
        lin1_w   = (const float*)d_in[3];  lin1_b   = (const float*)d_in[4];
        lin2_w   = (const float*)d_in[5];  lin2_b   = (const float*)d_in[6];
        w1 = (const float*)d_in[7];  b1 = (const float*)d_in[8];
        w2 = (const float*)d_in[9];  b2 = (const float*)d_in[10];
        lap_val  = (const float*)d_in[11]; mlp_ratio = (const float*)d_in[12];
        lap_row  = (const int*)d_in[13];   lap_col   = (const int*)d_in[14];
        user_idx = (const int*)d_in[15];   pos_idx   = (const int*)d_in[16];
        neg_idx  = (const int*)d_in[17];
    } else {
        user_emb = (const float*)d_in[0];  item_emb = (const float*)d_in[1];
        lin1_w   = (const float*)d_in[2];  lin1_b   = (const float*)d_in[3];
        lin2_w   = (const float*)d_in[4];  lin2_b   = (const float*)d_in[5];
        w1 = (const float*)d_in[6];  b1 = (const float*)d_in[7];
        w2 = (const float*)d_in[8];  b2 = (const float*)d_in[9];
        lap_row  = (const int*)d_in[10];   lap_col  = (const int*)d_in[11];
        lap_val  = (const float*)d_in[12];
        user_idx = (const int*)d_in[13];   user_feat = (const float*)d_in[14];
        pos_idx  = (const int*)d_in[15];   neg_idx   = (const int*)d_in[16];
        mlp_ratio= (const float*)d_in[17];
    }

    float* out = (float*)d_out;
    const int V4 = N_NODES * 16;

    // CSR build + weight split (independent of E; do them first)
    k_cnt_zero<<<NB_SCAN, 256>>>();
    k_hist<<<(NNZ + 255) / 256, 256>>>(lap_row);
    k_scan1<<<NB_SCAN, 256>>>();
    k_scan2<<<1, 1024>>>();
    k_scan3<<<NB_SCAN, 256>>>();
    k_fill<<<(NNZ + 255) / 256, 256>>>(lap_row, lap_col, lap_val);
    k_wsplit<<<(NLAYER * 64 * 128 + 255) / 256, 256>>>(w1, w2);

    k_mlp<<<BB, 64>>>(user_feat, lin1_w, lin1_b, lin2_w, lin2_b);
    k_init<<<(V4 + 255) / 256, 256>>>((const float4*)user_emb, (const float4*)item_emb);
    k_win_reset<<<(BB + 255) / 256, 256>>>(user_idx);
    k_win_max<<<(BB + 255) / 256, 256>>>(user_idx);
    k_apply<<<BB, 64>>>(user_idx, user_emb, mlp_ratio);
    k_gather<<<(3 * BB * 32 + 255) / 256, 256>>>(user_idx, pos_idx, neg_idx, out, 0);

    for (int k = 0; k < NLAYER; k++) {
        k_spmm_csr<<<(N_NODES / 2 + 7) / 8, 256>>>();
        k_gemm_mma<<<(N_NODES + 127) / 128, 256>>>(k, b1 + k * 64, b2 + k * 64);
        k_gather<<<(3 * BB * 32 + 255) / 256, 256>>>(user_idx, pos_idx, neg_idx, out, k + 1);
    }
}

// round 8
// speedup vs baseline: 1.2690x; 1.2328x over previous
#include <cuda_runtime.h>
#include <cuda_bf16.h>

#define N_USER  50000
#define N_ITEM  100000
#define N_NODES 150000
#define DD      64
#define NLAYER  3
#define NNZ     2400000
#define BB      1024
#define NB_SCAN 587   // ceil(N_NODES/256)
#define WPITCHB 68    // bf16-pair pitch per n row (64 pairs + 4 pad)

// Scratch (device globals: allocation-free per harness rules)
__device__ float4 g_E [N_NODES * 16];   // E  [N,64] as float4
__device__ float4 g_LE[N_NODES * 16];   // L_E[N,64] as float4
__device__ float  g_mlp[BB * DD];
__device__ int    g_win[N_USER];
// CSR scratch
__device__ int    g_cnt[N_NODES];
__device__ int    g_ptr[N_NODES];
__device__ int    g_cur[N_NODES];
__device__ int    g_bsum[NB_SCAN];
__device__ int    g_bscan[NB_SCAN];
__device__ int2   g_cv[NNZ];            // {col, float_as_int(val)}
// bf16 double-split transposed weights: [layer][n(64)][pair k/2 padded to 68]
__device__ unsigned int g_whiB[NLAYER * 64 * WPITCHB];
__device__ unsigned int g_wloB[NLAYER * 64 * WPITCHB];

// split x into bf16 hi + bf16 lo (pairwise packed, low half = first elem)
__device__ __forceinline__ void split_pack(float a, float b,
                                           unsigned int& hi, unsigned int& lo) {
    __nv_bfloat162 h = __floats2bfloat162_rn(a, b);
    float ra = a - __low2float(h);
    float rb = b - __high2float(h);
    __nv_bfloat162 l = __floats2bfloat162_rn(ra, rb);
    hi = *reinterpret_cast<unsigned int*>(&h);
    lo = *reinterpret_cast<unsigned int*>(&l);
}

// ---------------- tiny MLP ----------------
__global__ void k_mlp(const float* __restrict__ feat,
                      const float* __restrict__ l1w, const float* __restrict__ l1b,
                      const float* __restrict__ l2w, const float* __restrict__ l2b) {
    __shared__ float h[32];
    int i = blockIdx.x, t = threadIdx.x;
    if (t < 32) {
        float s = l1b[t];
#pragma unroll
        for (int f = 0; f < 4; f++) s += feat[i * 4 + f] * l1w[f * 32 + t];
        h[t] = s;
    }
    __syncthreads();
    float s = l2b[t];
#pragma unroll
    for (int j = 0; j < 32; j++) s += h[j] * l2w[j * DD + t];
    g_mlp[i * DD + t] = s;
}

// ---------------- E = concat(user_emb, item_emb) ----------------
__global__ void k_init(const float4* __restrict__ ue, const float4* __restrict__ ie) {
    int i = blockIdx.x * blockDim.x + threadIdx.x;
    const int NU4 = N_USER * 16;
    if (i < NU4) g_E[i] = ue[i];
    else if (i < N_NODES * 16) g_E[i] = ie[i - NU4];
}

// ---------------- last-wins scatter of user updates ----------------
__global__ void k_win_reset(const int* __restrict__ ui) {
    int i = blockIdx.x * blockDim.x + threadIdx.x;
    if (i < BB) g_win[ui[i]] = -1;
}
__global__ void k_win_max(const int* __restrict__ ui) {
    int i = blockIdx.x * blockDim.x + threadIdx.x;
    if (i < BB) atomicMax(&g_win[ui[i]], i);
}
__global__ void k_apply(const int* __restrict__ ui, const float* __restrict__ user_emb,
                        const float* __restrict__ ratio) {
    int i = blockIdx.x, t = threadIdx.x;  // 64 threads
    int u = ui[i];
    if (g_win[u] != i) return;
    float r = *ratio;
    float* E = (float*)g_E;
    E[u * DD + t] = user_emb[u * DD + t] * (1.0f - r) + g_mlp[i * DD + t] * r;
}

// ================= CSR build =================
__global__ void k_cnt_zero() {
    int i = blockIdx.x * blockDim.x + threadIdx.x;
    if (i < N_NODES) g_cnt[i] = 0;
}
__global__ void k_hist(const int* __restrict__ row) {
    int e = blockIdx.x * blockDim.x + threadIdx.x;
    if (e < NNZ) atomicAdd(&g_cnt[row[e]], 1);
}
__global__ void k_scan1() {
    __shared__ int s[256];
    int t = threadIdx.x;
    int i = blockIdx.x * 256 + t;
    int v = (i < N_NODES) ? g_cnt[i] : 0;
    s[t] = v;
    __syncthreads();
#pragma unroll
    for (int off = 1; off < 256; off <<= 1) {
        int u = (t >= off) ? s[t - off] : 0;
        __syncthreads();
        s[t] += u;
        __syncthreads();
    }
    if (i < N_NODES) g_ptr[i] = s[t] - v;
    if (t == 255) g_bsum[blockIdx.x] = s[255];
}
__global__ void k_scan2() {
    __shared__ int s[1024];
    int t = threadIdx.x;
    int v = (t < NB_SCAN) ? g_bsum[t] : 0;
    s[t] = v;
    __syncthreads();
#pragma unroll
    for (int off = 1; off < 1024; off <<= 1) {
        int u = (t >= off) ? s[t - off] : 0;
        __syncthreads();
        s[t] += u;
        __syncthreads();
    }
    if (t < NB_SCAN) g_bscan[t] = s[t] - v;
}
__global__ void k_scan3() {
    int i = blockIdx.x * blockDim.x + threadIdx.x;
    if (i < N_NODES) {
        int p = g_ptr[i] + g_bscan[i >> 8];
        g_ptr[i] = p;
        g_cur[i] = p;
    }
}
__global__ void k_fill(const int* __restrict__ row, const int* __restrict__ col,
                       const float* __restrict__ val) {
    int e = blockIdx.x * blockDim.x + threadIdx.x;
    if (e >= NNZ) return;
    int r = row[e];
    int pos = atomicAdd(&g_cur[r], 1);
    g_cv[pos] = make_int2(col[e], __float_as_int(val[e]));
}

// ================= CSR SpMM: 2 rows per warp, 16 lanes x float4 per row =======
__global__ void __launch_bounds__(256) k_spmm_csr() {
    int w = (blockIdx.x * blockDim.x + threadIdx.x) >> 5;
    int lane = threadIdx.x & 31;
    int half = lane >> 4;       // which row this half-warp owns
    int hl = lane & 15;         // lane within half (float4 slot)
    int row = w * 2 + half;
    if (row >= N_NODES) return;
    int start = g_ptr[row];
    int end = start + g_cnt[row];
    const float4* __restrict__ E4 = (const float4*)g_E;

    float4 a0 = make_float4(0.f, 0.f, 0.f, 0.f);
    float4 a1 = make_float4(0.f, 0.f, 0.f, 0.f);
    float4 a2 = make_float4(0.f, 0.f, 0.f, 0.f);
    float4 a3 = make_float4(0.f, 0.f, 0.f, 0.f);
    int e = start;
    for (; e + 4 <= end; e += 4) {
        int2 cv0 = g_cv[e],     cv1 = g_cv[e + 1];
        int2 cv2 = g_cv[e + 2], cv3 = g_cv[e + 3];
        float4 x0 = E4[cv0.x * 16 + hl];
        float4 x1 = E4[cv1.x * 16 + hl];
        float4 x2 = E4[cv2.x * 16 + hl];
        float4 x3 = E4[cv3.x * 16 + hl];
        float v0 = __int_as_float(cv0.y), v1 = __int_as_float(cv1.y);
        float v2 = __int_as_float(cv2.y), v3 = __int_as_float(cv3.y);
        a0.x += v0 * x0.x; a0.y += v0 * x0.y; a0.z += v0 * x0.z; a0.w += v0 * x0.w;
        a1.x += v1 * x1.x; a1.y += v1 * x1.y; a1.z += v1 * x1.z; a1.w += v1 * x1.w;
        a2.x += v2 * x2.x; a2.y += v2 * x2.y; a2.z += v2 * x2.z; a2.w += v2 * x2.w;
        a3.x += v3 * x3.x; a3.y += v3 * x3.y; a3.z += v3 * x3.z; a3.w += v3 * x3.w;
    }
    for (; e < end; e++) {
        int2 cv = g_cv[e];
        float4 x = E4[cv.x * 16 + hl];
        float v = __int_as_float(cv.y);
        a0.x += v * x.x; a0.y += v * x.y; a0.z += v * x.z; a0.w += v * x.w;
    }
    a0.x += a1.x + a2.x + a3.x;
    a0.y += a1.y + a2.y + a3.y;
    a0.z += a1.z + a2.z + a3.z;
    a0.w += a1.w + a2.w + a3.w;
    g_LE[row * 16 + hl] = a0;
}

// ================= W split (bf16 hi/lo pairs), transposed + padded ============
__global__ void k_wsplit(const float* __restrict__ w1, const float* __restrict__ w2) {
    int idx = blockIdx.x * 256 + threadIdx.x;  // over NLAYER*64*64 pairs
    if (idx >= NLAYER * 64 * 64) return;
    int layer = idx / 4096;
    int rem = idx % 4096;
    int n = rem >> 6, p = rem & 63;
    int k0 = 2 * p, k1 = 2 * p + 1;
    float wa = (k0 < 64) ? w1[layer * 4096 + k0 * 64 + n]
                         : w2[layer * 4096 + (k0 - 64) * 64 + n];
    float wb = (k1 < 64) ? w1[layer * 4096 + k1 * 64 + n]
                         : w2[layer * 4096 + (k1 - 64) * 64 + n];
    unsigned int hi, lo;
    split_pack(wa, wb, hi, lo);
    g_whiB[layer * 64 * WPITCHB + n * WPITCHB + p] = hi;
    g_wloB[layer * 64 * WPITCHB + n * WPITCHB + p] = lo;
}

// ================= tensor-core GEMM (bf16 double-split, m16n8k16) =============
// C[150K x 64] = [LE+E | LE*E] @ [w1;w2], one warp per 16 rows
#define MMA_BF16(C, A0, A1, A2, A3, B0, B1)                                      \
    asm volatile("mma.sync.aligned.m16n8k16.row.col.f32.bf16.bf16.f32 "          \
                 "{%0,%1,%2,%3}, {%4,%5,%6,%7}, {%8,%9}, {%0,%1,%2,%3};"         \
                 : "+f"(C[0]), "+f"(C[1]), "+f"(C[2]), "+f"(C[3])                \
                 : "r"(A0), "r"(A1), "r"(A2), "r"(A3), "r"(B0), "r"(B1))

__global__ void __launch_bounds__(256) k_gemm_mma(int layer,
                                                  const float* __restrict__ b1,
                                                  const float* __restrict__ b2) {
    __shared__ unsigned int whi[64 * WPITCHB];
    __shared__ float bs[64];
    int t = threadIdx.x;
    {
        const uint4* s4 = (const uint4*)(g_whiB + layer * 64 * WPITCHB);
        uint4* d4 = (uint4*)whi;
        for (int i = t; i < 64 * WPITCHB / 4; i += 256) d4[i] = s4[i];
        if (t < 64) bs[t] = b1[t] + b2[t];
    }
    __syncthreads();

    int warp = t >> 5, lane = t & 31;
    int q = lane & 3, g = lane >> 2;
    int base = blockIdx.x * 128 + warp * 16;
    int r0 = base + g, r1 = base + g + 8;
    int r0c = min(r0, N_NODES - 1), r1c = min(r1, N_NODES - 1);
    const float* __restrict__ Ei = (const float*)g_E;
    const float* __restrict__ LE = (const float*)g_LE;
    const unsigned int* __restrict__ wlo = g_wloB + layer * 64 * WPITCHB;

    float C[8][4];
#pragma unroll
    for (int i = 0; i < 8; i++)
#pragma unroll
        for (int j = 0; j < 4; j++) C[i][j] = 0.f;

#pragma unroll
    for (int kk = 0; kk < 8; kk++) {         // kk16 chunks of K=128
        int half = kk >> 2;                  // 0: (LE+E), 1: (LE*E)
        int cb = (kk & 3) * 16;
        int cA = cb + 2 * q;                 // k = 2q, 2q+1
        int cB = cA + 8;                     // k = 2q+8, 2q+9
        float2 lA0 = *(const float2*)(LE + r0c * 64 + cA);
        float2 lB0 = *(const float2*)(LE + r0c * 64 + cB);
        float2 lA1 = *(const float2*)(LE + r1c * 64 + cA);
        float2 lB1 = *(const float2*)(LE + r1c * 64 + cB);
        float2 eA0 = *(const float2*)(Ei + r0c * 64 + cA);
        float2 eB0 = *(const float2*)(Ei + r0c * 64 + cB);
        float2 eA1 = *(const float2*)(Ei + r1c * 64 + cA);
        float2 eB1 = *(const float2*)(Ei + r1c * 64 + cB);
        float2 xA0, xB0, xA1, xB1;
        if (half) {
            xA0 = make_float2(lA0.x * eA0.x, lA0.y * eA0.y);
            xB0 = make_float2(lB0.x * eB0.x, lB0.y * eB0.y);
            xA1 = make_float2(lA1.x * eA1.x, lA1.y * eA1.y);
            xB1 = make_float2(lB1.x * eB1.x, lB1.y * eB1.y);
        } else {
            xA0 = make_float2(lA0.x + eA0.x, lA0.y + eA0.y);
            xB0 = make_float2(lB0.x + eB0.x, lB0.y + eB0.y);
            xA1 = make_float2(lA1.x + eA1.x, lA1.y + eA1.y);
            xB1 = make_float2(lB1.x + eB1.x, lB1.y + eB1.y);
        }
        // A fragments: R0=row g k-lo, R1=row g+8 k-lo, R2=row g k-hi, R3=row g+8 k-hi
        unsigned int ah0, ah1, ah2, ah3, al0, al1, al2, al3;
        split_pack(xA0.x, xA0.y, ah0, al0);
        split_pack(xA1.x, xA1.y, ah1, al1);
        split_pack(xB0.x, xB0.y, ah2, al2);
        split_pack(xB1.x, xB1.y, ah3, al3);
        int kp = kk * 8 + q;                 // bf16-pair index
#pragma unroll
        for (int nt = 0; nt < 8; nt++) {
            int wb = (nt * 8 + g) * WPITCHB + kp;
            unsigned int bh0 = whi[wb], bh1 = whi[wb + 4];
            unsigned int bl0 = __ldg(&wlo[wb]), bl1 = __ldg(&wlo[wb + 4]);
            MMA_BF16(C[nt], ah0, ah1, ah2, ah3, bh0, bh1);
            MMA_BF16(C[nt], al0, al1, al2, al3, bh0, bh1);
            MMA_BF16(C[nt], ah0, ah1, ah2, ah3, bl0, bl1);
        }
    }

    float* Eo = (float*)g_E;
#pragma unroll
    for (int nt = 0; nt < 8; nt++) {
        int col = nt * 8 + 2 * q;
        float b0v = bs[col], b1v = bs[col + 1];
        float v00 = C[nt][0] + b0v, v01 = C[nt][1] + b1v;
        float v10 = C[nt][2] + b0v, v11 = C[nt][3] + b1v;
        v00 = v00 >= 0.f ? v00 : 0.2f * v00;
        v01 = v01 >= 0.f ? v01 : 0.2f * v01;
        v10 = v10 >= 0.f ? v10 : 0.2f * v10;
        v11 = v11 >= 0.f ? v11 : 0.2f * v11;
        if (r0 < N_NODES) *(float2*)(Eo + r0 * 64 + col) = make_float2(v00, v01);
        if (r1 < N_NODES) *(float2*)(Eo + r1 * 64 + col) = make_float2(v10, v11);
    }
}

// ---------------- gather (with optional row-normalize) into output ----------------
__global__ void k_gather(const int* __restrict__ user_idx, const int* __restrict__ pos_idx,
                         const int* __restrict__ neg_idx, float* __restrict__ out, int layer) {
    int w = (blockIdx.x * blockDim.x + threadIdx.x) >> 5;
    int lane = threadIdx.x & 31;
    if (w >= 3 * BB) return;
    int node;
    if (w < BB)          node = user_idx[w];
    else if (w < 2 * BB) node = N_USER + pos_idx[w - BB];
    else                 node = N_USER + neg_idx[w - 2 * BB];
    float2 v = ((const float2*)g_E)[node * 32 + lane];
    float scale = 1.0f;
    if (layer > 0) {
        float s = v.x * v.x + v.y * v.y;
#pragma unroll
        for (int o = 16; o; o >>= 1) s += __shfl_xor_sync(0xffffffffu, s, o);
        scale = 1.0f / fmaxf(sqrtf(s), 1e-12f);
    }
    ((float2*)(out + (size_t)w * 256 + layer * 64))[lane] = make_float2(v.x * scale, v.y * scale);
}

extern "C" void kernel_launch(void* const* d_in, const int* in_sizes, int n_in,
                              void* d_out, int out_size) {
    const float *user_emb, *item_emb, *lin1_w, *lin1_b, *lin2_w, *lin2_b;
    const float *w1, *b1, *w2, *b2, *lap_val, *user_feat, *mlp_ratio;
    const int *lap_row, *lap_col, *user_idx, *pos_idx, *neg_idx;

    if (in_sizes[2] == 4096) {
        user_emb = (const float*)d_in[0];  item_emb = (const float*)d_in[1];
        user_feat= (const float*)d_in[2];
        lin1_w   = (const float*)d_in[3];  lin1_b   = (const float*)d_in[4];
        lin2_w   = (const float*)d_in[5];  lin2_b   = (const float*)d_in[6];
        w1 = (const float*)d_in[7];  b1 = (const float*)d_in[8];
        w2 = (const float*)d_in[9];  b2 = (const float*)d_in[10];
        lap_val  = (const float*)d_in[11]; mlp_ratio = (const float*)d_in[12];
        lap_row  = (const int*)d_in[13];   lap_col   = (const int*)d_in[14];
        user_idx = (const int*)d_in[15];   pos_idx   = (const int*)d_in[16];
        neg_idx  = (const int*)d_in[17];
    } else {
        user_emb = (const float*)d_in[0];  item_emb = (const float*)d_in[1];
        lin1_w   = (const float*)d_in[2];  lin1_b   = (const float*)d_in[3];
        lin2_w   = (const float*)d_in[4];  lin2_b   = (const float*)d_in[5];
        w1 = (const float*)d_in[6];  b1 = (const float*)d_in[7];
        w2 = (const float*)d_in[8];  b2 = (const float*)d_in[9];
        lap_row  = (const int*)d_in[10];   lap_col  = (const int*)d_in[11];
        lap_val  = (const float*)d_in[12];
        user_idx = (const int*)d_in[13];   user_feat = (const float*)d_in[14];
        pos_idx  = (const int*)d_in[15];   neg_idx   = (const int*)d_in[16];
        mlp_ratio= (const float*)d_in[17];
    }

    float* out = (float*)d_out;
    const int V4 = N_NODES * 16;

    // CSR build + weight split (independent of E; do them first)
    k_cnt_zero<<<NB_SCAN, 256>>>();
    k_hist<<<(NNZ + 255) / 256, 256>>>(lap_row);
    k_scan1<<<NB_SCAN, 256>>>();
    k_scan2<<<1, 1024>>>();
    k_scan3<<<NB_SCAN, 256>>>();
    k_fill<<<(NNZ + 255) / 256, 256>>>(lap_row, lap_col, lap_val);
    k_wsplit<<<(NLAYER * 64 * 64 + 255) / 256, 256>>>(w1, w2);

    k_mlp<<<BB, 64>>>(user_feat, lin1_w, lin1_b, lin2_w, lin2_b);
    k_init<<<(V4 + 255) / 256, 256>>>((const float4*)user_emb, (const float4*)item_emb);
    k_win_reset<<<(BB + 255) / 256, 256>>>(user_idx);
    k_win_max<<<(BB + 255) / 256, 256>>>(user_idx);
    k_apply<<<BB, 64>>>(user_idx, user_emb, mlp_ratio);
    k_gather<<<(3 * BB * 32 + 255) / 256, 256>>>(user_idx, pos_idx, neg_idx, out, 0);

    for (int k = 0; k < NLAYER; k++) {
        k_spmm_csr<<<(N_NODES / 2 + 7) / 8, 256>>>();
        k_gemm_mma<<<(N_NODES + 127) / 128, 256>>>(k, b1 + k * 64, b2 + k * 64);
        k_gather<<<(3 * BB * 32 + 255) / 256, 256>>>(user_idx, pos_idx, neg_idx, out, k + 1);
    }
}

// round 9
// speedup vs baseline: 1.3167x; 1.0376x over previous
#include <cuda_runtime.h>
#include <cuda_bf16.h>

#define N_USER  50000
#define N_ITEM  100000
#define N_NODES 150000
#define DD      64
#define NLAYER  3
#define NNZ     2400000
#define BB      1024
#define NB_SCAN 587   // ceil(N_NODES/256)
#define WPITCHB 68    // bf16-pair pitch per n row (64 pairs + 4 pad)

#define NB_INIT   9375   // (N_NODES*16)/256 float4 slots
#define NB_WSPLIT 48     // ceil(NLAYER*64*64/256)
#define NB_MLP    256    // 1024 samples, 4 per 256-thread block
#define NB_HIST   9375   // ceil(NNZ/256)
#define NB_APPLY  256    // 1024 samples, 4 per block
#define NB_SPMM   9375   // N_NODES/2 warps / 8 per block
#define NB_GATHER 384    // 3*BB warps / 8 per block

// Scratch (device globals: allocation-free per harness rules)
__device__ float4 g_E [N_NODES * 16];   // E  [N,64] as float4
__device__ float4 g_LE[N_NODES * 16];   // L_E[N,64] as float4
__device__ float  g_mlp[BB * DD];
__device__ int    g_win[N_USER];
// CSR scratch
__device__ int    g_cnt[N_NODES];
__device__ int    g_ptr[N_NODES];
__device__ int    g_cur[N_NODES];
__device__ int    g_bsum[NB_SCAN];
__device__ int    g_bscan[NB_SCAN];
__device__ int2   g_cv[NNZ];            // {col, float_as_int(val)}
// bf16 double-split transposed weights: [layer][n(64)][pair k/2 padded to 68]
__device__ unsigned int g_whiB[NLAYER * 64 * WPITCHB];
__device__ unsigned int g_wloB[NLAYER * 64 * WPITCHB];

// split x into bf16 hi + bf16 lo (pairwise packed, low half = first elem)
__device__ __forceinline__ void split_pack(float a, float b,
                                           unsigned int& hi, unsigned int& lo) {
    __nv_bfloat162 h = __floats2bfloat162_rn(a, b);
    float ra = a - __low2float(h);
    float rb = b - __high2float(h);
    __nv_bfloat162 l = __floats2bfloat162_rn(ra, rb);
    hi = *reinterpret_cast<unsigned int*>(&h);
    lo = *reinterpret_cast<unsigned int*>(&l);
}

// ================= K_setup: init E + zero cnt + win_reset + wsplit + mlp ======
__global__ void __launch_bounds__(256) k_setup(
    const float4* __restrict__ ue, const float4* __restrict__ ie,
    const int* __restrict__ ui,
    const float* __restrict__ w1, const float* __restrict__ w2,
    const float* __restrict__ feat,
    const float* __restrict__ l1w, const float* __restrict__ l1b,
    const float* __restrict__ l2w, const float* __restrict__ l2b) {
    int b = blockIdx.x;
    int t = threadIdx.x;
    if (b < NB_INIT) {                                   // ---- E init
        int i = b * 256 + t;
        const int NU4 = N_USER * 16;
        if (i < NU4) g_E[i] = ue[i];
        else if (i < N_NODES * 16) g_E[i] = ie[i - NU4];
        return;
    }
    b -= NB_INIT;
    if (b < NB_SCAN) {                                   // ---- cnt zero
        int i = b * 256 + t;
        if (i < N_NODES) g_cnt[i] = 0;
        return;
    }
    b -= NB_SCAN;
    if (b < 4) {                                         // ---- win reset
        int i = b * 256 + t;
        if (i < BB) g_win[ui[i]] = -1;
        return;
    }
    b -= 4;
    if (b < NB_WSPLIT) {                                 // ---- w split
        int idx = b * 256 + t;
        if (idx >= NLAYER * 64 * 64) return;
        int layer = idx / 4096;
        int rem = idx % 4096;
        int n = rem >> 6, p = rem & 63;
        int k0 = 2 * p, k1 = 2 * p + 1;
        float wa = (k0 < 64) ? w1[layer * 4096 + k0 * 64 + n]
                             : w2[layer * 4096 + (k0 - 64) * 64 + n];
        float wb = (k1 < 64) ? w1[layer * 4096 + k1 * 64 + n]
                             : w2[layer * 4096 + (k1 - 64) * 64 + n];
        unsigned int hi, lo;
        split_pack(wa, wb, hi, lo);
        g_whiB[layer * 64 * WPITCHB + n * WPITCHB + p] = hi;
        g_wloB[layer * 64 * WPITCHB + n * WPITCHB + p] = lo;
        return;
    }
    b -= NB_WSPLIT;
    {                                                    // ---- mlp (4 samples/block)
        __shared__ float h[4][32];
        int s = t >> 6, u = t & 63;                      // sample slot, within
        int i = b * 4 + s;
        if (u < 32) {
            float acc = l1b[u];
#pragma unroll
            for (int f = 0; f < 4; f++) acc += feat[i * 4 + f] * l1w[f * 32 + u];
            h[s][u] = acc;
        }
        __syncthreads();
        float acc = l2b[u];
#pragma unroll
        for (int j = 0; j < 32; j++) acc += h[s][j] * l2w[j * DD + u];
        g_mlp[i * DD + u] = acc;
    }
}

// ================= K_hist2: histogram + win_max ===============================
__global__ void __launch_bounds__(256) k_hist2(const int* __restrict__ row,
                                               const int* __restrict__ ui) {
    int b = blockIdx.x;
    int t = threadIdx.x;
    if (b < NB_HIST) {
        int e = b * 256 + t;
        if (e < NNZ) atomicAdd(&g_cnt[row[e]], 1);
        return;
    }
    b -= NB_HIST;
    int i = b * 256 + t;
    if (i < BB) atomicMax(&g_win[ui[i]], i);
}

// ================= scans =================
__global__ void k_scan1() {
    __shared__ int s[256];
    int t = threadIdx.x;
    int i = blockIdx.x * 256 + t;
    int v = (i < N_NODES) ? g_cnt[i] : 0;
    s[t] = v;
    __syncthreads();
#pragma unroll
    for (int off = 1; off < 256; off <<= 1) {
        int u = (t >= off) ? s[t - off] : 0;
        __syncthreads();
        s[t] += u;
        __syncthreads();
    }
    if (i < N_NODES) g_ptr[i] = s[t] - v;
    if (t == 255) g_bsum[blockIdx.x] = s[255];
}
__global__ void k_scan2() {
    __shared__ int s[1024];
    int t = threadIdx.x;
    int v = (t < NB_SCAN) ? g_bsum[t] : 0;
    s[t] = v;
    __syncthreads();
#pragma unroll
    for (int off = 1; off < 1024; off <<= 1) {
        int u = (t >= off) ? s[t - off] : 0;
        __syncthreads();
        s[t] += u;
        __syncthreads();
    }
    if (t < NB_SCAN) g_bscan[t] = s[t] - v;
}
__global__ void k_scan3() {
    int i = blockIdx.x * blockDim.x + threadIdx.x;
    if (i < N_NODES) {
        int p = g_ptr[i] + g_bscan[i >> 8];
        g_ptr[i] = p;
        g_cur[i] = p;
    }
}

// ================= K_fill2: CSR fill + user-update apply ======================
__global__ void __launch_bounds__(256) k_fill2(const int* __restrict__ row,
                                               const int* __restrict__ col,
                                               const float* __restrict__ val,
                                               const int* __restrict__ ui,
                                               const float* __restrict__ user_emb,
                                               const float* __restrict__ ratio) {
    int b = blockIdx.x;
    int t = threadIdx.x;
    if (b < NB_HIST) {                                   // ---- fill
        int e = b * 256 + t;
        if (e >= NNZ) return;
        int r = row[e];
        int pos = atomicAdd(&g_cur[r], 1);
        g_cv[pos] = make_int2(col[e], __float_as_int(val[e]));
        return;
    }
    b -= NB_HIST;
    {                                                    // ---- apply (4 samples/block)
        int s = t >> 6, u64 = t & 63;
        int i = b * 4 + s;
        int u = ui[i];
        if (g_win[u] != i) return;
        float r = *ratio;
        float* E = (float*)g_E;
        E[u * DD + u64] = user_emb[u * DD + u64] * (1.0f - r) + g_mlp[i * DD + u64] * r;
    }
}

// ---------------- gather body (device fn) ----------------
__device__ __forceinline__ void gather_body(int w, int lane,
                                            const int* __restrict__ user_idx,
                                            const int* __restrict__ pos_idx,
                                            const int* __restrict__ neg_idx,
                                            float* __restrict__ out, int layer) {
    if (w >= 3 * BB) return;
    int node;
    if (w < BB)          node = user_idx[w];
    else if (w < 2 * BB) node = N_USER + pos_idx[w - BB];
    else                 node = N_USER + neg_idx[w - 2 * BB];
    float2 v = ((const float2*)g_E)[node * 32 + lane];
    float scale = 1.0f;
    if (layer > 0) {
        float s = v.x * v.x + v.y * v.y;
#pragma unroll
        for (int o = 16; o; o >>= 1) s += __shfl_xor_sync(0xffffffffu, s, o);
        scale = 1.0f / fmaxf(sqrtf(s), 1e-12f);
    }
    ((float2*)(out + (size_t)w * 256 + layer * 64))[lane] = make_float2(v.x * scale, v.y * scale);
}

__global__ void k_gather(const int* __restrict__ user_idx, const int* __restrict__ pos_idx,
                         const int* __restrict__ neg_idx, float* __restrict__ out, int layer) {
    int w = (blockIdx.x * blockDim.x + threadIdx.x) >> 5;
    gather_body(w, threadIdx.x & 31, user_idx, pos_idx, neg_idx, out, layer);
}

// ================= CSR SpMM (+fused gather of previous layer output) ==========
// blocks [0, NB_SPMM): spmm 2 rows/warp; blocks [NB_SPMM, +NB_GATHER): gather
__global__ void __launch_bounds__(256) k_spmm_g(const int* __restrict__ user_idx,
                                                const int* __restrict__ pos_idx,
                                                const int* __restrict__ neg_idx,
                                                float* __restrict__ out, int layer) {
    int lane = threadIdx.x & 31;
    if (blockIdx.x >= NB_SPMM) {
        if (layer >= 0) {
            int w = ((blockIdx.x - NB_SPMM) * blockDim.x + threadIdx.x) >> 5;
            gather_body(w, lane, user_idx, pos_idx, neg_idx, out, layer);
        }
        return;
    }
    int w = (blockIdx.x * blockDim.x + threadIdx.x) >> 5;
    int half = lane >> 4;
    int hl = lane & 15;
    int row = w * 2 + half;
    if (row >= N_NODES) return;
    int start = g_ptr[row];
    int end = start + g_cnt[row];
    const float4* __restrict__ E4 = (const float4*)g_E;

    float4 a0 = make_float4(0.f, 0.f, 0.f, 0.f);
    float4 a1 = make_float4(0.f, 0.f, 0.f, 0.f);
    float4 a2 = make_float4(0.f, 0.f, 0.f, 0.f);
    float4 a3 = make_float4(0.f, 0.f, 0.f, 0.f);
    int e = start;
    for (; e + 4 <= end; e += 4) {
        int2 cv0 = g_cv[e],     cv1 = g_cv[e + 1];
        int2 cv2 = g_cv[e + 2], cv3 = g_cv[e + 3];
        float4 x0 = E4[cv0.x * 16 + hl];
        float4 x1 = E4[cv1.x * 16 + hl];
        float4 x2 = E4[cv2.x * 16 + hl];
        float4 x3 = E4[cv3.x * 16 + hl];
        float v0 = __int_as_float(cv0.y), v1 = __int_as_float(cv1.y);
        float v2 = __int_as_float(cv2.y), v3 = __int_as_float(cv3.y);
        a0.x += v0 * x0.x; a0.y += v0 * x0.y; a0.z += v0 * x0.z; a0.w += v0 * x0.w;
        a1.x += v1 * x1.x; a1.y += v1 * x1.y; a1.z += v1 * x1.z; a1.w += v1 * x1.w;
        a2.x += v2 * x2.x; a2.y += v2 * x2.y; a2.z += v2 * x2.z; a2.w += v2 * x2.w;
        a3.x += v3 * x3.x; a3.y += v3 * x3.y; a3.z += v3 * x3.z; a3.w += v3 * x3.w;
    }
    for (; e < end; e++) {
        int2 cv = g_cv[e];
        float4 x = E4[cv.x * 16 + hl];
        float v = __int_as_float(cv.y);
        a0.x += v * x.x; a0.y += v * x.y; a0.z += v * x.z; a0.w += v * x.w;
    }
    a0.x += a1.x + a2.x + a3.x;
    a0.y += a1.y + a2.y + a3.y;
    a0.z += a1.z + a2.z + a3.z;
    a0.w += a1.w + a2.w + a3.w;
    g_LE[row * 16 + hl] = a0;
}

// ================= tensor-core GEMM (bf16 double-split, m16n8k16) =============
#define MMA_BF16(C, A0, A1, A2, A3, B0, B1)                                      \
    asm volatile("mma.sync.aligned.m16n8k16.row.col.f32.bf16.bf16.f32 "          \
                 "{%0,%1,%2,%3}, {%4,%5,%6,%7}, {%8,%9}, {%0,%1,%2,%3};"         \
                 : "+f"(C[0]), "+f"(C[1]), "+f"(C[2]), "+f"(C[3])                \
                 : "r"(A0), "r"(A1), "r"(A2), "r"(A3), "r"(B0), "r"(B1))

__global__ void __launch_bounds__(256) k_gemm_mma(int layer,
                                                  const float* __restrict__ b1,
                                                  const float* __restrict__ b2) {
    __shared__ unsigned int whi[64 * WPITCHB];
    __shared__ float bs[64];
    int t = threadIdx.x;
    {
        const uint4* s4 = (const uint4*)(g_whiB + layer * 64 * WPITCHB);
        uint4* d4 = (uint4*)whi;
        for (int i = t; i < 64 * WPITCHB / 4; i += 256) d4[i] = s4[i];
        if (t < 64) bs[t] = b1[t] + b2[t];
    }
    __syncthreads();

    int warp = t >> 5, lane = t & 31;
    int q = lane & 3, g = lane >> 2;
    int base = blockIdx.x * 128 + warp * 16;
    int r0 = base + g, r1 = base + g + 8;
    int r0c = min(r0, N_NODES - 1), r1c = min(r1, N_NODES - 1);
    const float* __restrict__ Ei = (const float*)g_E;
    const float* __restrict__ LE = (const float*)g_LE;
    const unsigned int* __restrict__ wlo = g_wloB + layer * 64 * WPITCHB;

    float C[8][4];
#pragma unroll
    for (int i = 0; i < 8; i++)
#pragma unroll
        for (int j = 0; j < 4; j++) C[i][j] = 0.f;

#pragma unroll
    for (int kk = 0; kk < 8; kk++) {         // kk16 chunks of K=128
        int half = kk >> 2;                  // 0: (LE+E), 1: (LE*E)
        int cb = (kk & 3) * 16;
        int cA = cb + 2 * q;
        int cB = cA + 8;
        float2 lA0 = *(const float2*)(LE + r0c * 64 + cA);
        float2 lB0 = *(const float2*)(LE + r0c * 64 + cB);
        float2 lA1 = *(const float2*)(LE + r1c * 64 + cA);
        float2 lB1 = *(const float2*)(LE + r1c * 64 + cB);
        float2 eA0 = *(const float2*)(Ei + r0c * 64 + cA);
        float2 eB0 = *(const float2*)(Ei + r0c * 64 + cB);
        float2 eA1 = *(const float2*)(Ei + r1c * 64 + cA);
        float2 eB1 = *(const float2*)(Ei + r1c * 64 + cB);
        float2 xA0, xB0, xA1, xB1;
        if (half) {
            xA0 = make_float2(lA0.x * eA0.x, lA0.y * eA0.y);
            xB0 = make_float2(lB0.x * eB0.x, lB0.y * eB0.y);
            xA1 = make_float2(lA1.x * eA1.x, lA1.y * eA1.y);
            xB1 = make_float2(lB1.x * eB1.x, lB1.y * eB1.y);
        } else {
            xA0 = make_float2(lA0.x + eA0.x, lA0.y + eA0.y);
            xB0 = make_float2(lB0.x + eB0.x, lB0.y + eB0.y);
            xA1 = make_float2(lA1.x + eA1.x, lA1.y + eA1.y);
            xB1 = make_float2(lB1.x + eB1.x, lB1.y + eB1.y);
        }
        unsigned int ah0, ah1, ah2, ah3, al0, al1, al2, al3;
        split_pack(xA0.x, xA0.y, ah0, al0);
        split_pack(xA1.x, xA1.y, ah1, al1);
        split_pack(xB0.x, xB0.y, ah2, al2);
        split_pack(xB1.x, xB1.y, ah3, al3);
        int kp = kk * 8 + q;
#pragma unroll
        for (int nt = 0; nt < 8; nt++) {
            int wb = (nt * 8 + g) * WPITCHB + kp;
            unsigned int bh0 = whi[wb], bh1 = whi[wb + 4];
            unsigned int bl0 = __ldg(&wlo[wb]), bl1 = __ldg(&wlo[wb + 4]);
            MMA_BF16(C[nt], ah0, ah1, ah2, ah3, bh0, bh1);
            MMA_BF16(C[nt], al0, al1, al2, al3, bh0, bh1);
            MMA_BF16(C[nt], ah0, ah1, ah2, ah3, bl0, bl1);
        }
    }

    float* Eo = (float*)g_E;
#pragma unroll
    for (int nt = 0; nt < 8; nt++) {
        int col = nt * 8 + 2 * q;
        float b0v = bs[col], b1v = bs[col + 1];
        float v00 = C[nt][0] + b0v, v01 = C[nt][1] + b1v;
        float v10 = C[nt][2] + b0v, v11 = C[nt][3] + b1v;
        v00 = v00 >= 0.f ? v00 : 0.2f * v00;
        v01 = v01 >= 0.f ? v01 : 0.2f * v01;
        v10 = v10 >= 0.f ? v10 : 0.2f * v10;
        v11 = v11 >= 0.f ? v11 : 0.2f * v11;
        if (r0 < N_NODES) *(float2*)(Eo + r0 * 64 + col) = make_float2(v00, v01);
        if (r1 < N_NODES) *(float2*)(Eo + r1 * 64 + col) = make_float2(v10, v11);
    }
}

extern "C" void kernel_launch(void* const* d_in, const int* in_sizes, int n_in,
                              void* d_out, int out_size) {
    const float *user_emb, *item_emb, *lin1_w, *lin1_b, *lin2_w, *lin2_b;
    const float *w1, *b1, *w2, *b2, *lap_val, *user_feat, *mlp_ratio;
    const int *lap_row, *lap_col, *user_idx, *pos_idx, *neg_idx;

    if (in_sizes[2] == 4096) {
        user_emb = (const float*)d_in[0];  item_emb = (const float*)d_in[1];
        user_feat= (const float*)d_in[2];
        lin1_w   = (const float*)d_in[3];  lin1_b   = (const float*)d_in[4];
        lin2_w   = (const float*)d_in[5];  lin2_b   = (const float*)d_in[6];
        w1 = (const float*)d_in[7];  b1 = (const float*)d_in[8];
        w2 = (const float*)d_in[9];  b2 = (const float*)d_in[10];
        lap_val  = (const float*)d_in[11]; mlp_ratio = (const float*)d_in[12];
        lap_row  = (const int*)d_in[13];   lap_col   = (const int*)d_in[14];
        user_idx = (const int*)d_in[15];   pos_idx   = (const int*)d_in[16];
        neg_idx  = (const int*)d_in[17];
    } else {
        user_emb = (const float*)d_in[0];  item_emb = (const float*)d_in[1];
        lin1_w   = (const float*)d_in[2];  lin1_b   = (const float*)d_in[3];
        lin2_w   = (const float*)d_in[4];  lin2_b   = (const float*)d_in[5];
        w1 = (const float*)d_in[6];  b1 = (const float*)d_in[7];
        w2 = (const float*)d_in[8];  b2 = (const float*)d_in[9];
        lap_row  = (const int*)d_in[10];   lap_col  = (const int*)d_in[11];
        lap_val  = (const float*)d_in[12];
        user_idx = (const int*)d_in[13];   user_feat = (const float*)d_in[14];
        pos_idx  = (const int*)d_in[15];   neg_idx   = (const int*)d_in[16];
        mlp_ratio= (const float*)d_in[17];
    }

    float* out = (float*)d_out;

    // phase 1: all independent setup work in one launch
    k_setup<<<NB_INIT + NB_SCAN + 4 + NB_WSPLIT + NB_MLP, 256>>>(
        (const float4*)user_emb, (const float4*)item_emb, user_idx,
        w1, w2, user_feat, lin1_w, lin1_b, lin2_w, lin2_b);
    // phase 2: histogram + winner selection
    k_hist2<<<NB_HIST + 4, 256>>>(lap_row, user_idx);
    // phase 3: scan chain
    k_scan1<<<NB_SCAN, 256>>>();
    k_scan2<<<1, 1024>>>();
    k_scan3<<<NB_SCAN, 256>>>();
    // phase 4: CSR fill + user-update apply
    k_fill2<<<NB_HIST + NB_APPLY, 256>>>(lap_row, lap_col, lap_val,
                                         user_idx, user_emb, mlp_ratio);
    // layer-0 gather
    k_gather<<<NB_GATHER, 256>>>(user_idx, pos_idx, neg_idx, out, 0);

    for (int k = 0; k < NLAYER; k++) {
        // spmm(k) fused with gather of layer-k output (k>0); layer=-1 disables
        k_spmm_g<<<NB_SPMM + NB_GATHER, 256>>>(user_idx, pos_idx, neg_idx, out,
                                               (k > 0) ? k : -1);
        k_gemm_mma<<<(N_NODES + 127) / 128, 256>>>(k, b1 + k * 64, b2 + k * 64);
    }
    // final gather after last gemm
    k_gather<<<NB_GATHER, 256>>>(user_idx, pos_idx, neg_idx, out, NLAYER);
}

// round 10
// speedup vs baseline: 1.3902x; 1.0558x over previous
#include <cuda_runtime.h>
#include <cuda_bf16.h>

#define N_USER  50000
#define N_ITEM  100000
#define N_NODES 150000
#define DD      64
#define NLAYER  3
#define NNZ     2400000
#define BB      1024
#define NB_SCAN 587   // ceil(N_NODES/256)
#define WPITCHB 68    // bf16-pair pitch per n row (64 pairs + 4 pad)

#define NB_INIT   9375   // (N_NODES*16)/256 float4 slots
#define NB_WSPLIT 48     // ceil(NLAYER*64*64/256)
#define NB_MLP    256    // 1024 samples, 4 per 256-thread block
#define NB_HIST   9375   // ceil(NNZ/256)
#define NB_APPLY  256    // 1024 samples, 4 per block
#define NB_SPMM   4688   // ceil((N_NODES/4 warps)/8 per block)
#define NB_GATHER 384    // 3*BB warps / 8 per block

// Scratch (device globals: allocation-free per harness rules)
__device__ float4 g_E [N_NODES * 16];   // E  [N,64] as float4
__device__ float4 g_LE[N_NODES * 16];   // L_E[N,64] as float4
__device__ float  g_mlp[BB * DD];
__device__ int    g_win[N_USER];
// CSR scratch
__device__ int    g_cnt[N_NODES];
__device__ int    g_ptr[N_NODES];
__device__ int    g_cur[N_NODES];
__device__ int    g_bsum[NB_SCAN];
__device__ int    g_bscan[NB_SCAN];
__device__ int2   g_cv[NNZ];            // {col, float_as_int(val)}
// bf16 double-split transposed weights: [layer][n(64)][pair k/2 padded to 68]
__device__ unsigned int g_whiB[NLAYER * 64 * WPITCHB];
__device__ unsigned int g_wloB[NLAYER * 64 * WPITCHB];

// split x into bf16 hi + bf16 lo (pairwise packed, low half = first elem)
__device__ __forceinline__ void split_pack(float a, float b,
                                           unsigned int& hi, unsigned int& lo) {
    __nv_bfloat162 h = __floats2bfloat162_rn(a, b);
    float ra = a - __low2float(h);
    float rb = b - __high2float(h);
    __nv_bfloat162 l = __floats2bfloat162_rn(ra, rb);
    hi = *reinterpret_cast<unsigned int*>(&h);
    lo = *reinterpret_cast<unsigned int*>(&l);
}

// ================= K_setup: init E + zero cnt + win_reset + wsplit + mlp ======
__global__ void __launch_bounds__(256) k_setup(
    const float4* __restrict__ ue, const float4* __restrict__ ie,
    const int* __restrict__ ui,
    const float* __restrict__ w1, const float* __restrict__ w2,
    const float* __restrict__ feat,
    const float* __restrict__ l1w, const float* __restrict__ l1b,
    const float* __restrict__ l2w, const float* __restrict__ l2b) {
    int b = blockIdx.x;
    int t = threadIdx.x;
    if (b < NB_INIT) {                                   // ---- E init
        int i = b * 256 + t;
        const int NU4 = N_USER * 16;
        if (i < NU4) g_E[i] = ue[i];
        else if (i < N_NODES * 16) g_E[i] = ie[i - NU4];
        return;
    }
    b -= NB_INIT;
    if (b < NB_SCAN) {                                   // ---- cnt zero
        int i = b * 256 + t;
        if (i < N_NODES) g_cnt[i] = 0;
        return;
    }
    b -= NB_SCAN;
    if (b < 4) {                                         // ---- win reset
        int i = b * 256 + t;
        if (i < BB) g_win[ui[i]] = -1;
        return;
    }
    b -= 4;
    if (b < NB_WSPLIT) {                                 // ---- w split
        int idx = b * 256 + t;
        if (idx >= NLAYER * 64 * 64) return;
        int layer = idx / 4096;
        int rem = idx % 4096;
        int n = rem >> 6, p = rem & 63;
        int k0 = 2 * p, k1 = 2 * p + 1;
        float wa = (k0 < 64) ? w1[layer * 4096 + k0 * 64 + n]
                             : w2[layer * 4096 + (k0 - 64) * 64 + n];
        float wb = (k1 < 64) ? w1[layer * 4096 + k1 * 64 + n]
                             : w2[layer * 4096 + (k1 - 64) * 64 + n];
        unsigned int hi, lo;
        split_pack(wa, wb, hi, lo);
        g_whiB[layer * 64 * WPITCHB + n * WPITCHB + p] = hi;
        g_wloB[layer * 64 * WPITCHB + n * WPITCHB + p] = lo;
        return;
    }
    b -= NB_WSPLIT;
    {                                                    // ---- mlp (4 samples/block)
        __shared__ float h[4][32];
        int s = t >> 6, u = t & 63;                      // sample slot, within
        int i = b * 4 + s;
        if (u < 32) {
            float acc = l1b[u];
#pragma unroll
            for (int f = 0; f < 4; f++) acc += feat[i * 4 + f] * l1w[f * 32 + u];
            h[s][u] = acc;
        }
        __syncthreads();
        float acc = l2b[u];
#pragma unroll
        for (int j = 0; j < 32; j++) acc += h[s][j] * l2w[j * DD + u];
        g_mlp[i * DD + u] = acc;
    }
}

// ================= K_hist2: histogram + win_max ===============================
__global__ void __launch_bounds__(256) k_hist2(const int* __restrict__ row,
                                               const int* __restrict__ ui) {
    int b = blockIdx.x;
    int t = threadIdx.x;
    if (b < NB_HIST) {
        int e = b * 256 + t;
        if (e < NNZ) atomicAdd(&g_cnt[row[e]], 1);
        return;
    }
    b -= NB_HIST;
    int i = b * 256 + t;
    if (i < BB) atomicMax(&g_win[ui[i]], i);
}

// ================= scans =================
__global__ void k_scan1() {
    __shared__ int s[256];
    int t = threadIdx.x;
    int i = blockIdx.x * 256 + t;
    int v = (i < N_NODES) ? g_cnt[i] : 0;
    s[t] = v;
    __syncthreads();
#pragma unroll
    for (int off = 1; off < 256; off <<= 1) {
        int u = (t >= off) ? s[t - off] : 0;
        __syncthreads();
        s[t] += u;
        __syncthreads();
    }
    if (i < N_NODES) g_ptr[i] = s[t] - v;
    if (t == 255) g_bsum[blockIdx.x] = s[255];
}
__global__ void k_scan2() {
    __shared__ int s[1024];
    int t = threadIdx.x;
    int v = (t < NB_SCAN) ? g_bsum[t] : 0;
    s[t] = v;
    __syncthreads();
#pragma unroll
    for (int off = 1; off < 1024; off <<= 1) {
        int u = (t >= off) ? s[t - off] : 0;
        __syncthreads();
        s[t] += u;
        __syncthreads();
    }
    if (t < NB_SCAN) g_bscan[t] = s[t] - v;
}
__global__ void k_scan3() {
    int i = blockIdx.x * blockDim.x + threadIdx.x;
    if (i < N_NODES) {
        int p = g_ptr[i] + g_bscan[i >> 8];
        g_ptr[i] = p;
        g_cur[i] = p;
    }
}

// ================= K_fill2: CSR fill + user-update apply ======================
__global__ void __launch_bounds__(256) k_fill2(const int* __restrict__ row,
                                               const int* __restrict__ col,
                                               const float* __restrict__ val,
                                               const int* __restrict__ ui,
                                               const float* __restrict__ user_emb,
                                               const float* __restrict__ ratio) {
    int b = blockIdx.x;
    int t = threadIdx.x;
    if (b < NB_HIST) {                                   // ---- fill
        int e = b * 256 + t;
        if (e >= NNZ) return;
        int r = row[e];
        int pos = atomicAdd(&g_cur[r], 1);
        g_cv[pos] = make_int2(col[e], __float_as_int(val[e]));
        return;
    }
    b -= NB_HIST;
    {                                                    // ---- apply (4 samples/block)
        int s = t >> 6, u64 = t & 63;
        int i = b * 4 + s;
        int u = ui[i];
        if (g_win[u] != i) return;
        float r = *ratio;
        float* E = (float*)g_E;
        E[u * DD + u64] = user_emb[u * DD + u64] * (1.0f - r) + g_mlp[i * DD + u64] * r;
    }
}

// ---------------- gather body (device fn) ----------------
__device__ __forceinline__ void gather_body(int w, int lane,
                                            const int* __restrict__ user_idx,
                                            const int* __restrict__ pos_idx,
                                            const int* __restrict__ neg_idx,
                                            float* __restrict__ out, int layer) {
    if (w >= 3 * BB) return;
    int node;
    if (w < BB)          node = user_idx[w];
    else if (w < 2 * BB) node = N_USER + pos_idx[w - BB];
    else                 node = N_USER + neg_idx[w - 2 * BB];
    float2 v = ((const float2*)g_E)[node * 32 + lane];
    float scale = 1.0f;
    if (layer > 0) {
        float s = v.x * v.x + v.y * v.y;
#pragma unroll
        for (int o = 16; o; o >>= 1) s += __shfl_xor_sync(0xffffffffu, s, o);
        scale = 1.0f / fmaxf(sqrtf(s), 1e-12f);
    }
    ((float2*)(out + (size_t)w * 256 + layer * 64))[lane] = make_float2(v.x * scale, v.y * scale);
}

__global__ void k_gather(const int* __restrict__ user_idx, const int* __restrict__ pos_idx,
                         const int* __restrict__ neg_idx, float* __restrict__ out, int layer) {
    int w = (blockIdx.x * blockDim.x + threadIdx.x) >> 5;
    gather_body(w, threadIdx.x & 31, user_idx, pos_idx, neg_idx, out, layer);
}

// ================= CSR SpMM: 4 rows/warp, 8 lanes x 2 float4 per row ==========
// blocks [0, NB_SPMM): spmm; blocks [NB_SPMM, +NB_GATHER): gather prev output
__global__ void __launch_bounds__(256) k_spmm_g(const int* __restrict__ user_idx,
                                                const int* __restrict__ pos_idx,
                                                const int* __restrict__ neg_idx,
                                                float* __restrict__ out, int layer) {
    int lane = threadIdx.x & 31;
    if (blockIdx.x >= NB_SPMM) {
        if (layer >= 0) {
            int w = ((blockIdx.x - NB_SPMM) * blockDim.x + threadIdx.x) >> 5;
            gather_body(w, lane, user_idx, pos_idx, neg_idx, out, layer);
        }
        return;
    }
    int w = (blockIdx.x * blockDim.x + threadIdx.x) >> 5;
    int sub = lane >> 3;        // 0..3: row within warp
    int hl = lane & 7;          // float4 slot within row half
    int row = w * 4 + sub;
    if (row >= N_NODES) return;
    int start = g_ptr[row];
    int end = start + g_cnt[row];
    const float4* __restrict__ E4 = (const float4*)g_E;

    float4 aL0 = make_float4(0.f, 0.f, 0.f, 0.f);
    float4 aH0 = make_float4(0.f, 0.f, 0.f, 0.f);
    float4 aL1 = make_float4(0.f, 0.f, 0.f, 0.f);
    float4 aH1 = make_float4(0.f, 0.f, 0.f, 0.f);
    int e = start;
    for (; e + 2 <= end; e += 2) {
        int2 c0 = g_cv[e], c1 = g_cv[e + 1];
        const float4* p0 = E4 + c0.x * 16 + hl;
        const float4* p1 = E4 + c1.x * 16 + hl;
        float4 xL0 = p0[0], xH0 = p0[8];
        float4 xL1 = p1[0], xH1 = p1[8];
        float v0 = __int_as_float(c0.y), v1 = __int_as_float(c1.y);
        aL0.x += v0 * xL0.x; aL0.y += v0 * xL0.y; aL0.z += v0 * xL0.z; aL0.w += v0 * xL0.w;
        aH0.x += v0 * xH0.x; aH0.y += v0 * xH0.y; aH0.z += v0 * xH0.z; aH0.w += v0 * xH0.w;
        aL1.x += v1 * xL1.x; aL1.y += v1 * xL1.y; aL1.z += v1 * xL1.z; aL1.w += v1 * xL1.w;
        aH1.x += v1 * xH1.x; aH1.y += v1 * xH1.y; aH1.z += v1 * xH1.z; aH1.w += v1 * xH1.w;
    }
    if (e < end) {
        int2 c0 = g_cv[e];
        const float4* p0 = E4 + c0.x * 16 + hl;
        float4 xL0 = p0[0], xH0 = p0[8];
        float v0 = __int_as_float(c0.y);
        aL0.x += v0 * xL0.x; aL0.y += v0 * xL0.y; aL0.z += v0 * xL0.z; aL0.w += v0 * xL0.w;
        aH0.x += v0 * xH0.x; aH0.y += v0 * xH0.y; aH0.z += v0 * xH0.z; aH0.w += v0 * xH0.w;
    }
    aL0.x += aL1.x; aL0.y += aL1.y; aL0.z += aL1.z; aL0.w += aL1.w;
    aH0.x += aH1.x; aH0.y += aH1.y; aH0.z += aH1.z; aH0.w += aH1.w;
    g_LE[row * 16 + hl] = aL0;
    g_LE[row * 16 + hl + 8] = aH0;
}

// ================= tensor-core GEMM (bf16 double-split, m16n8k16) =============
#define MMA_BF16(C, A0, A1, A2, A3, B0, B1)                                      \
    asm volatile("mma.sync.aligned.m16n8k16.row.col.f32.bf16.bf16.f32 "          \
                 "{%0,%1,%2,%3}, {%4,%5,%6,%7}, {%8,%9}, {%0,%1,%2,%3};"         \
                 : "+f"(C[0]), "+f"(C[1]), "+f"(C[2]), "+f"(C[3])                \
                 : "r"(A0), "r"(A1), "r"(A2), "r"(A3), "r"(B0), "r"(B1))

__global__ void __launch_bounds__(256) k_gemm_mma(int layer,
                                                  const float* __restrict__ b1,
                                                  const float* __restrict__ b2) {
    __shared__ unsigned int whi[64 * WPITCHB];
    __shared__ float bs[64];
    int t = threadIdx.x;
    {
        const uint4* s4 = (const uint4*)(g_whiB + layer * 64 * WPITCHB);
        uint4* d4 = (uint4*)whi;
        for (int i = t; i < 64 * WPITCHB / 4; i += 256) d4[i] = s4[i];
        if (t < 64) bs[t] = b1[t] + b2[t];
    }
    __syncthreads();

    int warp = t >> 5, lane = t & 31;
    int q = lane & 3, g = lane >> 2;
    int base = blockIdx.x * 128 + warp * 16;
    int r0 = base + g, r1 = base + g + 8;
    int r0c = min(r0, N_NODES - 1), r1c = min(r1, N_NODES - 1);
    const float* __restrict__ Ei = (const float*)g_E;
    const float* __restrict__ LE = (const float*)g_LE;
    const unsigned int* __restrict__ wlo = g_wloB + layer * 64 * WPITCHB;

    float C[8][4];
#pragma unroll
    for (int i = 0; i < 8; i++)
#pragma unroll
        for (int j = 0; j < 4; j++) C[i][j] = 0.f;

#pragma unroll
    for (int kk = 0; kk < 8; kk++) {         // kk16 chunks of K=128
        int half = kk >> 2;                  // 0: (LE+E), 1: (LE*E)
        int cb = (kk & 3) * 16;
        int cA = cb + 2 * q;
        int cB = cA + 8;
        float2 lA0 = *(const float2*)(LE + r0c * 64 + cA);
        float2 lB0 = *(const float2*)(LE + r0c * 64 + cB);
        float2 lA1 = *(const float2*)(LE + r1c * 64 + cA);
        float2 lB1 = *(const float2*)(LE + r1c * 64 + cB);
        float2 eA0 = *(const float2*)(Ei + r0c * 64 + cA);
        float2 eB0 = *(const float2*)(Ei + r0c * 64 + cB);
        float2 eA1 = *(const float2*)(Ei + r1c * 64 + cA);
        float2 eB1 = *(const float2*)(Ei + r1c * 64 + cB);
        float2 xA0, xB0, xA1, xB1;
        if (half) {
            xA0 = make_float2(lA0.x * eA0.x, lA0.y * eA0.y);
            xB0 = make_float2(lB0.x * eB0.x, lB0.y * eB0.y);
            xA1 = make_float2(lA1.x * eA1.x, lA1.y * eA1.y);
            xB1 = make_float2(lB1.x * eB1.x, lB1.y * eB1.y);
        } else {
            xA0 = make_float2(lA0.x + eA0.x, lA0.y + eA0.y);
            xB0 = make_float2(lB0.x + eB0.x, lB0.y + eB0.y);
            xA1 = make_float2(lA1.x + eA1.x, lA1.y + eA1.y);
            xB1 = make_float2(lB1.x + eB1.x, lB1.y + eB1.y);
        }
        unsigned int ah0, ah1, ah2, ah3, al0, al1, al2, al3;
        split_pack(xA0.x, xA0.y, ah0, al0);
        split_pack(xA1.x, xA1.y, ah1, al1);
        split_pack(xB0.x, xB0.y, ah2, al2);
        split_pack(xB1.x, xB1.y, ah3, al3);
        int kp = kk * 8 + q;
#pragma unroll
        for (int nt = 0; nt < 8; nt++) {
            int wb = (nt * 8 + g) * WPITCHB + kp;
            unsigned int bh0 = whi[wb], bh1 = whi[wb + 4];
            unsigned int bl0 = __ldg(&wlo[wb]), bl1 = __ldg(&wlo[wb + 4]);
            MMA_BF16(C[nt], ah0, ah1, ah2, ah3, bh0, bh1);
            MMA_BF16(C[nt], al0, al1, al2, al3, bh0, bh1);
            MMA_BF16(C[nt], ah0, ah1, ah2, ah3, bl0, bl1);
        }
    }

    float* Eo = (float*)g_E;
#pragma unroll
    for (int nt = 0; nt < 8; nt++) {
        int col = nt * 8 + 2 * q;
        float b0v = bs[col], b1v = bs[col + 1];
        float v00 = C[nt][0] + b0v, v01 = C[nt][1] + b1v;
        float v10 = C[nt][2] + b0v, v11 = C[nt][3] + b1v;
        v00 = v00 >= 0.f ? v00 : 0.2f * v00;
        v01 = v01 >= 0.f ? v01 : 0.2f * v01;
        v10 = v10 >= 0.f ? v10 : 0.2f * v10;
        v11 = v11 >= 0.f ? v11 : 0.2f * v11;
        if (r0 < N_NODES) *(float2*)(Eo + r0 * 64 + col) = make_float2(v00, v01);
        if (r1 < N_NODES) *(float2*)(Eo + r1 * 64 + col) = make_float2(v10, v11);
    }
}

extern "C" void kernel_launch(void* const* d_in, const int* in_sizes, int n_in,
                              void* d_out, int out_size) {
    const float *user_emb, *item_emb, *lin1_w, *lin1_b, *lin2_w, *lin2_b;
    const float *w1, *b1, *w2, *b2, *lap_val, *user_feat, *mlp_ratio;
    const int *lap_row, *lap_col, *user_idx, *pos_idx, *neg_idx;

    if (in_sizes[2] == 4096) {
        user_emb = (const float*)d_in[0];  item_emb = (const float*)d_in[1];
        user_feat= (const float*)d_in[2];
        lin1_w   = (const float*)d_in[3];  lin1_b   = (const float*)d_in[4];
        lin2_w   = (const float*)d_in[5];  lin2_b   = (const float*)d_in[6];
        w1 = (const float*)d_in[7];  b1 = (const float*)d_in[8];
        w2 = (const float*)d_in[9];  b2 = (const float*)d_in[10];
        lap_val  = (const float*)d_in[11]; mlp_ratio = (const float*)d_in[12];
        lap_row  = (const int*)d_in[13];   lap_col   = (const int*)d_in[14];
        user_idx = (const int*)d_in[15];   pos_idx   = (const int*)d_in[16];
        neg_idx  = (const int*)d_in[17];
    } else {
        user_emb = (const float*)d_in[0];  item_emb = (const float*)d_in[1];
        lin1_w   = (const float*)d_in[2];  lin1_b   = (const float*)d_in[3];
        lin2_w   = (const float*)d_in[4];  lin2_b   = (const float*)d_in[5];
        w1 = (const float*)d_in[6];  b1 = (const float*)d_in[7];
        w2 = (const float*)d_in[8];  b2 = (const float*)d_in[9];
        lap_row  = (const int*)d_in[10];   lap_col  = (const int*)d_in[11];
        lap_val  = (const float*)d_in[12];
        user_idx = (const int*)d_in[13];   user_feat = (const float*)d_in[14];
        pos_idx  = (const int*)d_in[15];   neg_idx   = (const int*)d_in[16];
        mlp_ratio= (const float*)d_in[17];
    }

    float* out = (float*)d_out;

    // phase 1: all independent setup work in one launch
    k_setup<<<NB_INIT + NB_SCAN + 4 + NB_WSPLIT + NB_MLP, 256>>>(
        (const float4*)user_emb, (const float4*)item_emb, user_idx,
        w1, w2, user_feat, lin1_w, lin1_b, lin2_w, lin2_b);
    // phase 2: histogram + winner selection
    k_hist2<<<NB_HIST + 4, 256>>>(lap_row, user_idx);
    // phase 3: scan chain
    k_scan1<<<NB_SCAN, 256>>>();
    k_scan2<<<1, 1024>>>();
    k_scan3<<<NB_SCAN, 256>>>();
    // phase 4: CSR fill + user-update apply
    k_fill2<<<NB_HIST + NB_APPLY, 256>>>(lap_row, lap_col, lap_val,
                                         user_idx, user_emb, mlp_ratio);
    // layer-0 gather
    k_gather<<<NB_GATHER, 256>>>(user_idx, pos_idx, neg_idx, out, 0);

    for (int k = 0; k < NLAYER; k++) {
        // spmm(k) fused with gather of layer-k output (k>0); layer=-1 disables
        k_spmm_g<<<NB_SPMM + NB_GATHER, 256>>>(user_idx, pos_idx, neg_idx, out,
                                               (k > 0) ? k : -1);
        k_gemm_mma<<<(N_NODES + 127) / 128, 256>>>(k, b1 + k * 64, b2 + k * 64);
    }
    // final gather after last gemm
    k_gather<<<NB_GATHER, 256>>>(user_idx, pos_idx, neg_idx, out, NLAYER);
}

// round 11
// speedup vs baseline: 1.4410x; 1.0366x over previous
#include <cuda_runtime.h>
#include <cuda_bf16.h>
#include <cuda_fp16.h>

#define N_USER  50000
#define N_ITEM  100000
#define N_NODES 150000
#define DD      64
#define NLAYER  3
#define NNZ     2400000
#define BB      1024
#define NB_SCAN 587   // ceil(N_NODES/256)
#define WPITCHB 68    // bf16-pair pitch per n row (64 pairs + 4 pad)

#define NB_INIT   9375   // (N_NODES*16)/256 float4 slots
#define NB_WSPLIT 48     // ceil(NLAYER*64*64/256)
#define NB_MLP    256    // 1024 samples, 4 per 256-thread block
#define NB_HIST   9375   // ceil(NNZ/256)
#define NB_APPLY  256    // 1024 samples, 4 per block
#define NB_SPMM   4688   // ceil((N_NODES/4 warps)/8 per block)
#define NB_GATHER 384    // 3*BB warps / 8 per block

// Scratch (device globals: allocation-free per harness rules)
__device__ float4 g_E [N_NODES * 16];   // E  [N,64] fp32
__device__ float4 g_LE[N_NODES * 16];   // L_E[N,64] fp32
__device__ uint2  g_Eh[N_NODES * 16];   // E  [N,64] fp16 shadow (4 halves/uint2)
__device__ float  g_mlp[BB * DD];
__device__ int    g_win[N_USER];
// CSR scratch
__device__ int    g_cnt[N_NODES];
__device__ int    g_ptr[N_NODES];
__device__ int    g_cur[N_NODES];
__device__ int    g_bsum[NB_SCAN];
__device__ int    g_bscan[NB_SCAN];
__device__ int2   g_cv[NNZ];            // {col, float_as_int(val)}
// bf16 double-split transposed weights: [layer][n(64)][pair k/2 padded to 68]
__device__ unsigned int g_whiB[NLAYER * 64 * WPITCHB];
__device__ unsigned int g_wloB[NLAYER * 64 * WPITCHB];

// split x into bf16 hi + bf16 lo (pairwise packed, low half = first elem)
__device__ __forceinline__ void split_pack(float a, float b,
                                           unsigned int& hi, unsigned int& lo) {
    __nv_bfloat162 h = __floats2bfloat162_rn(a, b);
    float ra = a - __low2float(h);
    float rb = b - __high2float(h);
    __nv_bfloat162 l = __floats2bfloat162_rn(ra, rb);
    hi = *reinterpret_cast<unsigned int*>(&h);
    lo = *reinterpret_cast<unsigned int*>(&l);
}

__device__ __forceinline__ uint2 pack_half4(float4 v) {
    __half2 a = __floats2half2_rn(v.x, v.y);
    __half2 b = __floats2half2_rn(v.z, v.w);
    uint2 r;
    r.x = *reinterpret_cast<unsigned int*>(&a);
    r.y = *reinterpret_cast<unsigned int*>(&b);
    return r;
}
// accumulate 8 halves (uint4) scaled by v into two float4 accumulators
__device__ __forceinline__ void acc8(float4& a, float4& b, float v, uint4 u) {
    float2 f0 = __half22float2(*reinterpret_cast<__half2*>(&u.x));
    float2 f1 = __half22float2(*reinterpret_cast<__half2*>(&u.y));
    float2 f2 = __half22float2(*reinterpret_cast<__half2*>(&u.z));
    float2 f3 = __half22float2(*reinterpret_cast<__half2*>(&u.w));
    a.x += v * f0.x; a.y += v * f0.y; a.z += v * f1.x; a.w += v * f1.y;
    b.x += v * f2.x; b.y += v * f2.y; b.z += v * f3.x; b.w += v * f3.y;
}

// ================= K_setup: init E + zero cnt + win_reset + wsplit + mlp ======
__global__ void __launch_bounds__(256) k_setup(
    const float4* __restrict__ ue, const float4* __restrict__ ie,
    const int* __restrict__ ui,
    const float* __restrict__ w1, const float* __restrict__ w2,
    const float* __restrict__ feat,
    const float* __restrict__ l1w, const float* __restrict__ l1b,
    const float* __restrict__ l2w, const float* __restrict__ l2b) {
    int b = blockIdx.x;
    int t = threadIdx.x;
    if (b < NB_INIT) {                                   // ---- E init (fp32+fp16)
        int i = b * 256 + t;
        const int NU4 = N_USER * 16;
        if (i >= N_NODES * 16) return;
        float4 v = (i < NU4) ? ue[i] : ie[i - NU4];
        g_E[i] = v;
        g_Eh[i] = pack_half4(v);
        return;
    }
    b -= NB_INIT;
    if (b < NB_SCAN) {                                   // ---- cnt zero
        int i = b * 256 + t;
        if (i < N_NODES) g_cnt[i] = 0;
        return;
    }
    b -= NB_SCAN;
    if (b < 4) {                                         // ---- win reset
        int i = b * 256 + t;
        if (i < BB) g_win[ui[i]] = -1;
        return;
    }
    b -= 4;
    if (b < NB_WSPLIT) {                                 // ---- w split
        int idx = b * 256 + t;
        if (idx >= NLAYER * 64 * 64) return;
        int layer = idx / 4096;
        int rem = idx % 4096;
        int n = rem >> 6, p = rem & 63;
        int k0 = 2 * p, k1 = 2 * p + 1;
        float wa = (k0 < 64) ? w1[layer * 4096 + k0 * 64 + n]
                             : w2[layer * 4096 + (k0 - 64) * 64 + n];
        float wb = (k1 < 64) ? w1[layer * 4096 + k1 * 64 + n]
                             : w2[layer * 4096 + (k1 - 64) * 64 + n];
        unsigned int hi, lo;
        split_pack(wa, wb, hi, lo);
        g_whiB[layer * 64 * WPITCHB + n * WPITCHB + p] = hi;
        g_wloB[layer * 64 * WPITCHB + n * WPITCHB + p] = lo;
        return;
    }
    b -= NB_WSPLIT;
    {                                                    // ---- mlp (4 samples/block)
        __shared__ float h[4][32];
        int s = t >> 6, u = t & 63;                      // sample slot, within
        int i = b * 4 + s;
        if (u < 32) {
            float acc = l1b[u];
#pragma unroll
            for (int f = 0; f < 4; f++) acc += feat[i * 4 + f] * l1w[f * 32 + u];
            h[s][u] = acc;
        }
        __syncthreads();
        float acc = l2b[u];
#pragma unroll
        for (int j = 0; j < 32; j++) acc += h[s][j] * l2w[j * DD + u];
        g_mlp[i * DD + u] = acc;
    }
}

// ================= K_hist2: histogram + win_max ===============================
__global__ void __launch_bounds__(256) k_hist2(const int* __restrict__ row,
                                               const int* __restrict__ ui) {
    int b = blockIdx.x;
    int t = threadIdx.x;
    if (b < NB_HIST) {
        int e = b * 256 + t;
        if (e < NNZ) atomicAdd(&g_cnt[row[e]], 1);
        return;
    }
    b -= NB_HIST;
    int i = b * 256 + t;
    if (i < BB) atomicMax(&g_win[ui[i]], i);
}

// ================= scans =================
__global__ void k_scan1() {
    __shared__ int s[256];
    int t = threadIdx.x;
    int i = blockIdx.x * 256 + t;
    int v = (i < N_NODES) ? g_cnt[i] : 0;
    s[t] = v;
    __syncthreads();
#pragma unroll
    for (int off = 1; off < 256; off <<= 1) {
        int u = (t >= off) ? s[t - off] : 0;
        __syncthreads();
        s[t] += u;
        __syncthreads();
    }
    if (i < N_NODES) g_ptr[i] = s[t] - v;
    if (t == 255) g_bsum[blockIdx.x] = s[255];
}
__global__ void k_scan2() {
    __shared__ int s[1024];
    int t = threadIdx.x;
    int v = (t < NB_SCAN) ? g_bsum[t] : 0;
    s[t] = v;
    __syncthreads();
#pragma unroll
    for (int off = 1; off < 1024; off <<= 1) {
        int u = (t >= off) ? s[t - off] : 0;
        __syncthreads();
        s[t] += u;
        __syncthreads();
    }
    if (t < NB_SCAN) g_bscan[t] = s[t] - v;
}
__global__ void k_scan3() {
    int i = blockIdx.x * blockDim.x + threadIdx.x;
    if (i < N_NODES) {
        int p = g_ptr[i] + g_bscan[i >> 8];
        g_ptr[i] = p;
        g_cur[i] = p;
    }
}

// ================= K_fill2: CSR fill + user-update apply ======================
__global__ void __launch_bounds__(256) k_fill2(const int* __restrict__ row,
                                               const int* __restrict__ col,
                                               const float* __restrict__ val,
                                               const int* __restrict__ ui,
                                               const float* __restrict__ user_emb,
                                               const float* __restrict__ ratio) {
    int b = blockIdx.x;
    int t = threadIdx.x;
    if (b < NB_HIST) {                                   // ---- fill
        int e = b * 256 + t;
        if (e >= NNZ) return;
        int r = row[e];
        int pos = atomicAdd(&g_cur[r], 1);
        g_cv[pos] = make_int2(col[e], __float_as_int(val[e]));
        return;
    }
    b -= NB_HIST;
    {                                                    // ---- apply (4 samples/block)
        int s = t >> 6, u64 = t & 63;
        int i = b * 4 + s;
        int u = ui[i];
        if (g_win[u] != i) return;
        float r = *ratio;
        float* E = (float*)g_E;
        float v = user_emb[u * DD + u64] * (1.0f - r) + g_mlp[i * DD + u64] * r;
        E[u * DD + u64] = v;
        ((__half*)g_Eh)[u * DD + u64] = __float2half_rn(v);
    }
}

// ---------------- gather body (device fn) ----------------
__device__ __forceinline__ void gather_body(int w, int lane,
                                            const int* __restrict__ user_idx,
                                            const int* __restrict__ pos_idx,
                                            const int* __restrict__ neg_idx,
                                            float* __restrict__ out, int layer) {
    if (w >= 3 * BB) return;
    int node;
    if (w < BB)          node = user_idx[w];
    else if (w < 2 * BB) node = N_USER + pos_idx[w - BB];
    else                 node = N_USER + neg_idx[w - 2 * BB];
    float2 v = ((const float2*)g_E)[node * 32 + lane];
    float scale = 1.0f;
    if (layer > 0) {
        float s = v.x * v.x + v.y * v.y;
#pragma unroll
        for (int o = 16; o; o >>= 1) s += __shfl_xor_sync(0xffffffffu, s, o);
        scale = 1.0f / fmaxf(sqrtf(s), 1e-12f);
    }
    ((float2*)(out + (size_t)w * 256 + layer * 64))[lane] = make_float2(v.x * scale, v.y * scale);
}

__global__ void k_gather(const int* __restrict__ user_idx, const int* __restrict__ pos_idx,
                         const int* __restrict__ neg_idx, float* __restrict__ out, int layer) {
    int w = (blockIdx.x * blockDim.x + threadIdx.x) >> 5;
    gather_body(w, threadIdx.x & 31, user_idx, pos_idx, neg_idx, out, layer);
}

// ================= CSR SpMM (fp16 gather): 4 rows/warp, 8 lanes x uint4/row ===
// blocks [0, NB_SPMM): spmm; blocks [NB_SPMM, +NB_GATHER): gather prev output
__global__ void __launch_bounds__(256) k_spmm_g(const int* __restrict__ user_idx,
                                                const int* __restrict__ pos_idx,
                                                const int* __restrict__ neg_idx,
                                                float* __restrict__ out, int layer) {
    int lane = threadIdx.x & 31;
    if (blockIdx.x >= NB_SPMM) {
        if (layer >= 0) {
            int w = ((blockIdx.x - NB_SPMM) * blockDim.x + threadIdx.x) >> 5;
            gather_body(w, lane, user_idx, pos_idx, neg_idx, out, layer);
        }
        return;
    }
    int w = (blockIdx.x * blockDim.x + threadIdx.x) >> 5;
    int sub = lane >> 3;        // 0..3: row within warp
    int hl = lane & 7;          // uint4 slot within fp16 row (8 halves each)
    int row = w * 4 + sub;
    if (row >= N_NODES) return;
    int start = g_ptr[row];
    int end = start + g_cnt[row];
    const uint4* __restrict__ Eh = (const uint4*)g_Eh;

    float4 aL0 = make_float4(0.f, 0.f, 0.f, 0.f);
    float4 aH0 = make_float4(0.f, 0.f, 0.f, 0.f);
    float4 aL1 = make_float4(0.f, 0.f, 0.f, 0.f);
    float4 aH1 = make_float4(0.f, 0.f, 0.f, 0.f);
    int e = start;
    for (; e + 2 <= end; e += 2) {
        int2 c0 = g_cv[e], c1 = g_cv[e + 1];
        uint4 x0 = Eh[c0.x * 8 + hl];       // full 128B row per 8 lanes
        uint4 x1 = Eh[c1.x * 8 + hl];
        acc8(aL0, aH0, __int_as_float(c0.y), x0);
        acc8(aL1, aH1, __int_as_float(c1.y), x1);
    }
    if (e < end) {
        int2 c0 = g_cv[e];
        uint4 x0 = Eh[c0.x * 8 + hl];
        acc8(aL0, aH0, __int_as_float(c0.y), x0);
    }
    aL0.x += aL1.x; aL0.y += aL1.y; aL0.z += aL1.z; aL0.w += aL1.w;
    aH0.x += aH1.x; aH0.y += aH1.y; aH0.z += aH1.z; aH0.w += aH1.w;
    // lane owns halves [hl*8, hl*8+8) = float4 slots 2*hl, 2*hl+1
    g_LE[row * 16 + 2 * hl] = aL0;
    g_LE[row * 16 + 2 * hl + 1] = aH0;
}

// ================= tensor-core GEMM (bf16 double-split, m16n8k16) =============
#define MMA_BF16(C, A0, A1, A2, A3, B0, B1)                                      \
    asm volatile("mma.sync.aligned.m16n8k16.row.col.f32.bf16.bf16.f32 "          \
                 "{%0,%1,%2,%3}, {%4,%5,%6,%7}, {%8,%9}, {%0,%1,%2,%3};"         \
                 : "+f"(C[0]), "+f"(C[1]), "+f"(C[2]), "+f"(C[3])                \
                 : "r"(A0), "r"(A1), "r"(A2), "r"(A3), "r"(B0), "r"(B1))

__global__ void __launch_bounds__(256) k_gemm_mma(int layer,
                                                  const float* __restrict__ b1,
                                                  const float* __restrict__ b2) {
    __shared__ unsigned int whi[64 * WPITCHB];
    __shared__ float bs[64];
    int t = threadIdx.x;
    {
        const uint4* s4 = (const uint4*)(g_whiB + layer * 64 * WPITCHB);
        uint4* d4 = (uint4*)whi;
        for (int i = t; i < 64 * WPITCHB / 4; i += 256) d4[i] = s4[i];
        if (t < 64) bs[t] = b1[t] + b2[t];
    }
    __syncthreads();

    int warp = t >> 5, lane = t & 31;
    int q = lane & 3, g = lane >> 2;
    int base = blockIdx.x * 128 + warp * 16;
    int r0 = base + g, r1 = base + g + 8;
    int r0c = min(r0, N_NODES - 1), r1c = min(r1, N_NODES - 1);
    const float* __restrict__ Ei = (const float*)g_E;
    const float* __restrict__ LE = (const float*)g_LE;
    const unsigned int* __restrict__ wlo = g_wloB + layer * 64 * WPITCHB;

    float C[8][4];
#pragma unroll
    for (int i = 0; i < 8; i++)
#pragma unroll
        for (int j = 0; j < 4; j++) C[i][j] = 0.f;

#pragma unroll
    for (int kk = 0; kk < 8; kk++) {         // kk16 chunks of K=128
        int half = kk >> 2;                  // 0: (LE+E), 1: (LE*E)
        int cb = (kk & 3) * 16;
        int cA = cb + 2 * q;
        int cB = cA + 8;
        float2 lA0 = *(const float2*)(LE + r0c * 64 + cA);
        float2 lB0 = *(const float2*)(LE + r0c * 64 + cB);
        float2 lA1 = *(const float2*)(LE + r1c * 64 + cA);
        float2 lB1 = *(const float2*)(LE + r1c * 64 + cB);
        float2 eA0 = *(const float2*)(Ei + r0c * 64 + cA);
        float2 eB0 = *(const float2*)(Ei + r0c * 64 + cB);
        float2 eA1 = *(const float2*)(Ei + r1c * 64 + cA);
        float2 eB1 = *(const float2*)(Ei + r1c * 64 + cB);
        float2 xA0, xB0, xA1, xB1;
        if (half) {
            xA0 = make_float2(lA0.x * eA0.x, lA0.y * eA0.y);
            xB0 = make_float2(lB0.x * eB0.x, lB0.y * eB0.y);
            xA1 = make_float2(lA1.x * eA1.x, lA1.y * eA1.y);
            xB1 = make_float2(lB1.x * eB1.x, lB1.y * eB1.y);
        } else {
            xA0 = make_float2(lA0.x + eA0.x, lA0.y + eA0.y);
            xB0 = make_float2(lB0.x + eB0.x, lB0.y + eB0.y);
            xA1 = make_float2(lA1.x + eA1.x, lA1.y + eA1.y);
            xB1 = make_float2(lB1.x + eB1.x, lB1.y + eB1.y);
        }
        unsigned int ah0, ah1, ah2, ah3, al0, al1, al2, al3;
        split_pack(xA0.x, xA0.y, ah0, al0);
        split_pack(xA1.x, xA1.y, ah1, al1);
        split_pack(xB0.x, xB0.y, ah2, al2);
        split_pack(xB1.x, xB1.y, ah3, al3);
        int kp = kk * 8 + q;
#pragma unroll
        for (int nt = 0; nt < 8; nt++) {
            int wb = (nt * 8 + g) * WPITCHB + kp;
            unsigned int bh0 = whi[wb], bh1 = whi[wb + 4];
            unsigned int bl0 = __ldg(&wlo[wb]), bl1 = __ldg(&wlo[wb + 4]);
            MMA_BF16(C[nt], ah0, ah1, ah2, ah3, bh0, bh1);
            MMA_BF16(C[nt], al0, al1, al2, al3, bh0, bh1);
            MMA_BF16(C[nt], ah0, ah1, ah2, ah3, bl0, bl1);
        }
    }

    float* Eo = (float*)g_E;
    __half2* Eoh = (__half2*)g_Eh;
#pragma unroll
    for (int nt = 0; nt < 8; nt++) {
        int col = nt * 8 + 2 * q;
        float b0v = bs[col], b1v = bs[col + 1];
        float v00 = C[nt][0] + b0v, v01 = C[nt][1] + b1v;
        float v10 = C[nt][2] + b0v, v11 = C[nt][3] + b1v;
        v00 = v00 >= 0.f ? v00 : 0.2f * v00;
        v01 = v01 >= 0.f ? v01 : 0.2f * v01;
        v10 = v10 >= 0.f ? v10 : 0.2f * v10;
        v11 = v11 >= 0.f ? v11 : 0.2f * v11;
        if (r0 < N_NODES) {
            *(float2*)(Eo + r0 * 64 + col) = make_float2(v00, v01);
            Eoh[r0 * 32 + col / 2] = __floats2half2_rn(v00, v01);
        }
        if (r1 < N_NODES) {
            *(float2*)(Eo + r1 * 64 + col) = make_float2(v10, v11);
            Eoh[r1 * 32 + col / 2] = __floats2half2_rn(v10, v11);
        }
    }
}

extern "C" void kernel_launch(void* const* d_in, const int* in_sizes, int n_in,
                              void* d_out, int out_size) {
    const float *user_emb, *item_emb, *lin1_w, *lin1_b, *lin2_w, *lin2_b;
    const float *w1, *b1, *w2, *b2, *lap_val, *user_feat, *mlp_ratio;
    const int *lap_row, *lap_col, *user_idx, *pos_idx, *neg_idx;

    if (in_sizes[2] == 4096) {
        user_emb = (const float*)d_in[0];  item_emb = (const float*)d_in[1];
        user_feat= (const float*)d_in[2];
        lin1_w   = (const float*)d_in[3];  lin1_b   = (const float*)d_in[4];
        lin2_w   = (const float*)d_in[5];  lin2_b   = (const float*)d_in[6];
        w1 = (const float*)d_in[7];  b1 = (const float*)d_in[8];
        w2 = (const float*)d_in[9];  b2 = (const float*)d_in[10];
        lap_val  = (const float*)d_in[11]; mlp_ratio = (const float*)d_in[12];
        lap_row  = (const int*)d_in[13];   lap_col   = (const int*)d_in[14];
        user_idx = (const int*)d_in[15];   pos_idx   = (const int*)d_in[16];
        neg_idx  = (const int*)d_in[17];
    } else {
        user_emb = (const float*)d_in[0];  item_emb = (const float*)d_in[1];
        lin1_w   = (const float*)d_in[2];  lin1_b   = (const float*)d_in[3];
        lin2_w   = (const float*)d_in[4];  lin2_b   = (const float*)d_in[5];
        w1 = (const float*)d_in[6];  b1 = (const float*)d_in[7];
        w2 = (const float*)d_in[8];  b2 = (const float*)d_in[9];
        lap_row  = (const int*)d_in[10];   lap_col  = (const int*)d_in[11];
        lap_val  = (const float*)d_in[12];
        user_idx = (const int*)d_in[13];   user_feat = (const float*)d_in[14];
        pos_idx  = (const int*)d_in[15];   neg_idx   = (const int*)d_in[16];
        mlp_ratio= (const float*)d_in[17];
    }

    float* out = (float*)d_out;

    // phase 1: all independent setup work in one launch
    k_setup<<<NB_INIT + NB_SCAN + 4 + NB_WSPLIT + NB_MLP, 256>>>(
        (const float4*)user_emb, (const float4*)item_emb, user_idx,
        w1, w2, user_feat, lin1_w, lin1_b, lin2_w, lin2_b);
    // phase 2: histogram + winner selection
    k_hist2<<<NB_HIST + 4, 256>>>(lap_row, user_idx);
    // phase 3: scan chain
    k_scan1<<<NB_SCAN, 256>>>();
    k_scan2<<<1, 1024>>>();
    k_scan3<<<NB_SCAN, 256>>>();
    // phase 4: CSR fill + user-update apply
    k_fill2<<<NB_HIST + NB_APPLY, 256>>>(lap_row, lap_col, lap_val,
                                         user_idx, user_emb, mlp_ratio);
    // layer-0 gather
    k_gather<<<NB_GATHER, 256>>>(user_idx, pos_idx, neg_idx, out, 0);

    for (int k = 0; k < NLAYER; k++) {
        // spmm(k) fused with gather of layer-k output (k>0); layer=-1 disables
        k_spmm_g<<<NB_SPMM + NB_GATHER, 256>>>(user_idx, pos_idx, neg_idx, out,
                                               (k > 0) ? k : -1);
        k_gemm_mma<<<(N_NODES + 127) / 128, 256>>>(k, b1 + k * 64, b2 + k * 64);
    }
    // final gather after last gemm
    k_gather<<<NB_GATHER, 256>>>(user_idx, pos_idx, neg_idx, out, NLAYER);
}